// round 1
// baseline (speedup 1.0000x reference)
#include <cuda_runtime.h>
#include <cuda_fp16.h>
#include <cstdint>

#define NN   50000
#define EE   800000
#define EMB  16
#define KW   128
#define NCONV 4

// ---------------- device scratch (no cudaMalloc allowed) ----------------
__device__ float  d_W[(size_t)EE * 256];      // per-edge 16x16 weight matrices (fp32)
__device__ float  d_hA[NN * EMB];
__device__ float  d_hB[NN * EMB];
__device__ float  d_agg[NN * EMB];
__device__ float  d_cnt[NN];
__device__ __half d_k2h[KW * KW], d_k2l[KW * KW];     // k2_w transposed [n][k], hi/lo split
__device__ __half d_k3h[256 * KW], d_k3l[256 * KW];   // k3_w transposed [n][k], hi/lo split
__device__ int    d_is64;

// ---------------- helpers ----------------
__device__ __forceinline__ void mma16816(float* c,
    uint32_t a0, uint32_t a1, uint32_t a2, uint32_t a3,
    uint32_t b0, uint32_t b1)
{
    asm volatile(
        "mma.sync.aligned.m16n8k16.row.col.f32.f16.f16.f32 "
        "{%0,%1,%2,%3},{%4,%5,%6,%7},{%8,%9},{%0,%1,%2,%3};\n"
        : "+f"(c[0]), "+f"(c[1]), "+f"(c[2]), "+f"(c[3])
        : "r"(a0), "r"(a1), "r"(a2), "r"(a3), "r"(b0), "r"(b1));
}

// ---------------- kernels ----------------

// Detect whether edge_index is int64 (high 32-bit words all zero) or int32.
__global__ void k_detect(const int* __restrict__ ei)
{
    __shared__ int anynz;
    if (threadIdx.x == 0) anynz = 0;
    __syncthreads();
    int v = ei[2 * threadIdx.x + 1];   // 256 probes, well inside buffer
    if (v != 0) atomicOr(&anynz, 1);
    __syncthreads();
    if (threadIdx.x == 0) d_is64 = (anynz == 0) ? 1 : 0;
}

// Transpose + fp16 hi/lo split the k2/k3 weights once per launch.
__global__ void k_prep(const float* __restrict__ k2w, const float* __restrict__ k3w)
{
    int t = blockIdx.x * blockDim.x + threadIdx.x;
    if (t < KW * KW) {
        int n = t >> 7, k = t & 127;
        float v = k2w[k * KW + n];
        __half h = __float2half_rn(v);
        d_k2h[t] = h;
        d_k2l[t] = __float2half_rn(v - __half2float(h));
    } else if (t < KW * KW + 256 * KW) {
        int t2 = t - KW * KW;
        int n = t2 >> 7, k = t2 & 127;
        float v = k3w[k * 256 + n];
        __half h = __float2half_rn(v);
        d_k3h[t2] = h;
        d_k3l[t2] = __float2half_rn(v - __half2float(h));
    }
}

// h0 = x @ emb_w + emb_b ; zero agg & counts
__global__ void k_init(const float* __restrict__ x,
                       const float* __restrict__ emb_w,
                       const float* __restrict__ emb_b)
{
    int t = blockIdx.x * blockDim.x + threadIdx.x;
    if (t >= NN * EMB) return;
    int n = t >> 4, o = t & 15;
    float v = emb_b[o];
    #pragma unroll
    for (int f = 0; f < 3; f++) v += x[n * 3 + f] * emb_w[f * EMB + o];
    d_hA[t]  = v;
    d_agg[t] = 0.f;
    if (o == 0) d_cnt[n] = 0.f;
}

__global__ void k_cnt(const void* __restrict__ ei)
{
    long long e = (long long)blockIdx.x * blockDim.x + threadIdx.x;
    if (e >= EE) return;
    long long dst;
    if (d_is64) dst = ((const long long*)ei)[EE + e];
    else        dst = ((const int*)ei)[EE + e];
    atomicAdd(&d_cnt[dst], 1.f);
}

// Fused edge-MLP: 128 edges per block.
// layer1 fp32 scalar -> layers 2,3 via fp16 MMA with Markidis hi/lo correction.
__global__ __launch_bounds__(256, 1) void k_mlp(
    const float* __restrict__ ea,
    const float* __restrict__ k1w, const float* __restrict__ k1b,
    const float* __restrict__ k2b, const float* __restrict__ k3b)
{
    const int ST = KW + 8;   // smem row stride in halves (conflict-free)
    extern __shared__ __half sm[];
    __half* Ah = sm;
    __half* Al = Ah + 128 * ST;
    __half* Bh = Al + 128 * ST;
    __half* Bl = Bh + 128 * ST;

    const int tid  = threadIdx.x;
    const int warp = tid >> 5;
    const int lane = tid & 31;
    const int g    = lane >> 2;      // group id 0..7
    const int tg   = lane & 3;       // thread-in-group
    const long long ebase = (long long)blockIdx.x * 128;

    // ---- stage 1: e1 = relu(ea @ k1_w + k1_b), split to fp16 hi/lo in smem ----
    {
        int r  = tid >> 1;
        int j0 = (tid & 1) * 64;
        float a[6];
        const float* earow = ea + (ebase + r) * 6;
        #pragma unroll
        for (int f = 0; f < 6; f++) a[f] = earow[f];
        for (int jj = 0; jj < 64; jj++) {
            int j = j0 + jj;
            float v = k1b[j];
            #pragma unroll
            for (int f = 0; f < 6; f++) v = fmaf(a[f], k1w[f * KW + j], v);
            v = fmaxf(v, 0.f);
            __half h = __float2half_rn(v);
            Ah[r * ST + j] = h;
            Al[r * ST + j] = __float2half_rn(v - __half2float(h));
        }
    }
    // stage B tile <- k2 (already transposed [n][k])
    for (int i = tid; i < KW * KW; i += 256) {
        int n = i >> 7, k = i & 127;
        Bh[n * ST + k] = d_k2h[i];
        Bl[n * ST + k] = d_k2l[i];
    }
    __syncthreads();

    const int r0 = warp * 16;    // each warp owns 16 rows

    // ---- stage 2: e2 = relu(e1 @ k2_w + k2_b) ----
    {
        float acc[16][4];
        #pragma unroll
        for (int nt = 0; nt < 16; nt++)
            acc[nt][0] = acc[nt][1] = acc[nt][2] = acc[nt][3] = 0.f;

        #pragma unroll
        for (int ks = 0; ks < 8; ks++) {
            int k0 = ks * 16 + tg * 2;
            uint32_t a0 = *(const uint32_t*)&Ah[(r0 + g    ) * ST + k0];
            uint32_t a1 = *(const uint32_t*)&Ah[(r0 + g + 8) * ST + k0];
            uint32_t a2 = *(const uint32_t*)&Ah[(r0 + g    ) * ST + k0 + 8];
            uint32_t a3 = *(const uint32_t*)&Ah[(r0 + g + 8) * ST + k0 + 8];
            uint32_t l0 = *(const uint32_t*)&Al[(r0 + g    ) * ST + k0];
            uint32_t l1 = *(const uint32_t*)&Al[(r0 + g + 8) * ST + k0];
            uint32_t l2 = *(const uint32_t*)&Al[(r0 + g    ) * ST + k0 + 8];
            uint32_t l3 = *(const uint32_t*)&Al[(r0 + g + 8) * ST + k0 + 8];
            #pragma unroll
            for (int nt = 0; nt < 16; nt++) {
                uint32_t b0 = *(const uint32_t*)&Bh[(nt * 8 + g) * ST + k0];
                uint32_t b1 = *(const uint32_t*)&Bh[(nt * 8 + g) * ST + k0 + 8];
                uint32_t c0 = *(const uint32_t*)&Bl[(nt * 8 + g) * ST + k0];
                uint32_t c1 = *(const uint32_t*)&Bl[(nt * 8 + g) * ST + k0 + 8];
                mma16816(acc[nt], a0, a1, a2, a3, b0, b1);
                mma16816(acc[nt], l0, l1, l2, l3, b0, b1);
                mma16816(acc[nt], a0, a1, a2, a3, c0, c1);
            }
        }
        // relu + bias, write e2 back over A (each warp touches only its own rows)
        #pragma unroll
        for (int nt = 0; nt < 16; nt++) {
            #pragma unroll
            for (int q = 0; q < 4; q++) {
                int row = r0 + g + (q >> 1) * 8;
                int col = nt * 8 + tg * 2 + (q & 1);
                float v = acc[nt][q] + k2b[col];
                v = fmaxf(v, 0.f);
                __half h = __float2half_rn(v);
                Ah[row * ST + col] = h;
                Al[row * ST + col] = __float2half_rn(v - __half2float(h));
            }
        }
    }

    // ---- stage 3: W = e2 @ k3_w + k3_b  (two 128-col halves, reuse B smem) ----
    for (int half = 0; half < 2; half++) {
        __syncthreads();   // all warps done reading current B tile
        for (int i = tid; i < KW * KW; i += 256) {
            int n = i >> 7, k = i & 127;
            Bh[n * ST + k] = d_k3h[(half * 128 + n) * KW + k];
            Bl[n * ST + k] = d_k3l[(half * 128 + n) * KW + k];
        }
        __syncthreads();

        float acc[16][4];
        #pragma unroll
        for (int nt = 0; nt < 16; nt++)
            acc[nt][0] = acc[nt][1] = acc[nt][2] = acc[nt][3] = 0.f;

        #pragma unroll
        for (int ks = 0; ks < 8; ks++) {
            int k0 = ks * 16 + tg * 2;
            uint32_t a0 = *(const uint32_t*)&Ah[(r0 + g    ) * ST + k0];
            uint32_t a1 = *(const uint32_t*)&Ah[(r0 + g + 8) * ST + k0];
            uint32_t a2 = *(const uint32_t*)&Ah[(r0 + g    ) * ST + k0 + 8];
            uint32_t a3 = *(const uint32_t*)&Ah[(r0 + g + 8) * ST + k0 + 8];
            uint32_t l0 = *(const uint32_t*)&Al[(r0 + g    ) * ST + k0];
            uint32_t l1 = *(const uint32_t*)&Al[(r0 + g + 8) * ST + k0];
            uint32_t l2 = *(const uint32_t*)&Al[(r0 + g    ) * ST + k0 + 8];
            uint32_t l3 = *(const uint32_t*)&Al[(r0 + g + 8) * ST + k0 + 8];
            #pragma unroll
            for (int nt = 0; nt < 16; nt++) {
                uint32_t b0 = *(const uint32_t*)&Bh[(nt * 8 + g) * ST + k0];
                uint32_t b1 = *(const uint32_t*)&Bh[(nt * 8 + g) * ST + k0 + 8];
                uint32_t c0 = *(const uint32_t*)&Bl[(nt * 8 + g) * ST + k0];
                uint32_t c1 = *(const uint32_t*)&Bl[(nt * 8 + g) * ST + k0 + 8];
                mma16816(acc[nt], a0, a1, a2, a3, b0, b1);
                mma16816(acc[nt], l0, l1, l2, l3, b0, b1);
                mma16816(acc[nt], a0, a1, a2, a3, c0, c1);
            }
        }
        // write W (fp32) to global
        #pragma unroll
        for (int nt = 0; nt < 16; nt++) {
            #pragma unroll
            for (int q = 0; q < 4; q++) {
                int row = r0 + g + (q >> 1) * 8;
                int col = half * 128 + nt * 8 + tg * 2 + (q & 1);
                d_W[(ebase + row) * 256 + col] = acc[nt][q] + k3b[col];
            }
        }
    }
}

// msg = h[src] @ W_e ; atomic scatter-add into agg[dst]
__global__ void k_conv(const void* __restrict__ ei, const float* __restrict__ hin)
{
    long long e = (long long)blockIdx.x * 8 + (threadIdx.x >> 4);
    int o = threadIdx.x & 15;
    if (e >= EE) return;
    long long src, dst;
    if (d_is64) {
        const long long* p = (const long long*)ei;
        src = p[e]; dst = p[EE + e];
    } else {
        const int* p = (const int*)ei;
        src = p[e]; dst = p[EE + e];
    }
    const float* hr = hin + src * EMB;
    const float* Wr = d_W + e * 256;
    float m = 0.f;
    #pragma unroll
    for (int i = 0; i < 16; i++) m = fmaf(hr[i], Wr[i * 16 + o], m);
    atomicAdd(&d_agg[dst * EMB + o], m);
}

// h_out = relu(agg/denom + h_in @ root_w + conv_b); zero agg for next round
__global__ void k_update(const float* __restrict__ hin, float* __restrict__ hout,
                         const float* __restrict__ root_w, const float* __restrict__ conv_b)
{
    int t = blockIdx.x * blockDim.x + threadIdx.x;
    if (t >= NN * EMB) return;
    int n = t >> 4, o = t & 15;
    float denom = fmaxf(d_cnt[n], 1.f);
    float v = d_agg[t] / denom;
    const float* hr = hin + n * EMB;
    #pragma unroll
    for (int i = 0; i < 16; i++) v = fmaf(hr[i], root_w[i * EMB + o], v);
    v += conv_b[o];
    hout[t] = fmaxf(v, 0.f);
    d_agg[t] = 0.f;
}

__global__ void k_out(const float* __restrict__ hin,
                      const float* __restrict__ inv_w, const float* __restrict__ inv_b,
                      float* __restrict__ out)
{
    int t = blockIdx.x * blockDim.x + threadIdx.x;
    if (t >= NN * 3) return;
    int n = t / 3, f = t % 3;
    float v = inv_b[f];
    const float* hr = hin + n * EMB;
    #pragma unroll
    for (int i = 0; i < 16; i++) v = fmaf(hr[i], inv_w[i * 3 + f], v);
    out[t] = v;
}

// ---------------- launcher ----------------
extern "C" void kernel_launch(void* const* d_in, const int* in_sizes, int n_in,
                              void* d_out, int out_size)
{
    const float* x      = (const float*)d_in[0];
    const void*  ei     = d_in[1];
    const float* ea     = (const float*)d_in[2];
    const float* emb_w  = (const float*)d_in[3];
    const float* emb_b  = (const float*)d_in[4];
    const float* k1_w   = (const float*)d_in[5];
    const float* k1_b   = (const float*)d_in[6];
    const float* k2_w   = (const float*)d_in[7];
    const float* k2_b   = (const float*)d_in[8];
    const float* k3_w   = (const float*)d_in[9];
    const float* k3_b   = (const float*)d_in[10];
    const float* root_w = (const float*)d_in[11];
    const float* conv_b = (const float*)d_in[12];
    const float* inv_w  = (const float*)d_in[13];
    const float* inv_b  = (const float*)d_in[14];
    float* out = (float*)d_out;

    const int ST = KW + 8;
    const int smemBytes = 4 * 128 * ST * (int)sizeof(__half);   // 139264
    cudaFuncSetAttribute(k_mlp, cudaFuncAttributeMaxDynamicSharedMemorySize, smemBytes);

    // resolve device scratch symbols for kernels that take them as args
    // (kernels reference the __device__ globals directly; only h ping-pong
    //  pointers are needed host-side)
    static float* hA = nullptr;
    static float* hB = nullptr;
    if (!hA) {
        cudaGetSymbolAddress((void**)&hA, d_hA);
        cudaGetSymbolAddress((void**)&hB, d_hB);
    }

    k_detect<<<1, 256>>>((const int*)ei);
    k_prep<<<(KW * KW + 256 * KW + 255) / 256, 256>>>(k2_w, k3_w);
    k_init<<<(NN * EMB + 255) / 256, 256>>>(x, emb_w, emb_b);
    k_cnt<<<(EE + 255) / 256, 256>>>(ei);
    k_mlp<<<EE / 128, 256, smemBytes>>>(ea, k1_w, k1_b, k2_b, k3_b);

    float* hin  = hA;
    float* hout = hB;
    for (int it = 0; it < NCONV; it++) {
        k_conv<<<EE / 8, 128>>>(ei, hin);
        k_update<<<(NN * EMB + 255) / 256, 256>>>(hin, hout, root_w, conv_b);
        float* tmp = hin; hin = hout; hout = tmp;
    }
    k_out<<<(NN * 3 + 255) / 256, 256>>>(hin, inv_w, inv_b, out);
}

// round 2
// speedup vs baseline: 1.9017x; 1.9017x over previous
#include <cuda_runtime.h>
#include <cuda_fp16.h>
#include <cstdint>

#define NN   50000
#define EE   800000
#define EMB  16
#define KW   128
#define NCONV 4

// ---------------- device scratch (no cudaMalloc allowed) ----------------
__device__ __half d_W[(size_t)EE * 256];      // per-edge 16x16 weight matrices (fp16)
__device__ float  d_hA[NN * EMB];
__device__ float  d_hB[NN * EMB];
__device__ float  d_agg[NN * EMB];
__device__ float  d_cnt[NN];
__device__ __half d_k2h[KW * KW];             // k2_w transposed [n][k]
__device__ __half d_k3h[256 * KW];            // k3_w transposed [n][k]
__device__ int    d_is64;

// ---------------- helpers ----------------
__device__ __forceinline__ void mma16816(float* c,
    uint32_t a0, uint32_t a1, uint32_t a2, uint32_t a3,
    uint32_t b0, uint32_t b1)
{
    asm volatile(
        "mma.sync.aligned.m16n8k16.row.col.f32.f16.f16.f32 "
        "{%0,%1,%2,%3},{%4,%5,%6,%7},{%8,%9},{%0,%1,%2,%3};\n"
        : "+f"(c[0]), "+f"(c[1]), "+f"(c[2]), "+f"(c[3])
        : "r"(a0), "r"(a1), "r"(a2), "r"(a3), "r"(b0), "r"(b1));
}

// ---------------- kernels ----------------

// Detect whether edge_index is int64 (high 32-bit words all zero) or int32.
__global__ void k_detect(const int* __restrict__ ei)
{
    __shared__ int anynz;
    if (threadIdx.x == 0) anynz = 0;
    __syncthreads();
    int v = ei[2 * threadIdx.x + 1];
    if (v != 0) atomicOr(&anynz, 1);
    __syncthreads();
    if (threadIdx.x == 0) d_is64 = (anynz == 0) ? 1 : 0;
}

// Transpose + fp16-convert k2/k3 weights once per launch.
__global__ void k_prep(const float* __restrict__ k2w, const float* __restrict__ k3w)
{
    int t = blockIdx.x * blockDim.x + threadIdx.x;
    if (t < KW * KW) {
        int n = t >> 7, k = t & 127;
        d_k2h[t] = __float2half_rn(k2w[k * KW + n]);
    } else if (t < KW * KW + 256 * KW) {
        int t2 = t - KW * KW;
        int n = t2 >> 7, k = t2 & 127;
        d_k3h[t2] = __float2half_rn(k3w[k * 256 + n]);
    }
}

// h0 = x @ emb_w + emb_b ; zero agg & counts
__global__ void k_init(const float* __restrict__ x,
                       const float* __restrict__ emb_w,
                       const float* __restrict__ emb_b)
{
    int t = blockIdx.x * blockDim.x + threadIdx.x;
    if (t >= NN * EMB) return;
    int n = t >> 4, o = t & 15;
    float v = emb_b[o];
    #pragma unroll
    for (int f = 0; f < 3; f++) v += x[n * 3 + f] * emb_w[f * EMB + o];
    d_hA[t]  = v;
    d_agg[t] = 0.f;
    if (o == 0) d_cnt[n] = 0.f;
}

__global__ void k_cnt(const void* __restrict__ ei)
{
    long long e = (long long)blockIdx.x * blockDim.x + threadIdx.x;
    if (e >= EE) return;
    long long dst;
    if (d_is64) dst = ((const long long*)ei)[EE + e];
    else        dst = ((const int*)ei)[EE + e];
    atomicAdd(&d_cnt[dst], 1.f);
}

// Fused edge-MLP: 128 edges per block, fp16 MMA, fp16 W output.
__global__ __launch_bounds__(256) void k_mlp(
    const float* __restrict__ ea,
    const float* __restrict__ k1w, const float* __restrict__ k1b,
    const float* __restrict__ k2b, const float* __restrict__ k3b)
{
    const int ST = KW + 8;   // smem row stride in halves (conflict-free)
    extern __shared__ __half sm[];
    __half* Ah = sm;                 // 128 x ST activations
    __half* Bh = Ah + 128 * ST;      // 128 x ST weight tile

    const int tid  = threadIdx.x;
    const int warp = tid >> 5;
    const int lane = tid & 31;
    const int g    = lane >> 2;      // group id 0..7
    const int tg   = lane & 3;       // thread-in-group
    const long long ebase = (long long)blockIdx.x * 128;

    // ---- stage 1: e1 = relu(ea @ k1_w + k1_b) -> fp16 smem ----
    {
        int r  = tid >> 1;
        int j0 = (tid & 1) * 64;
        float a[6];
        const float* earow = ea + (ebase + r) * 6;
        #pragma unroll
        for (int f = 0; f < 6; f++) a[f] = earow[f];
        for (int jj = 0; jj < 64; jj++) {
            int j = j0 + jj;
            float v = k1b[j];
            #pragma unroll
            for (int f = 0; f < 6; f++) v = fmaf(a[f], k1w[f * KW + j], v);
            Ah[r * ST + j] = __float2half_rn(fmaxf(v, 0.f));
        }
    }
    for (int i = tid; i < KW * KW; i += 256) {
        int n = i >> 7, k = i & 127;
        Bh[n * ST + k] = d_k2h[i];
    }
    __syncthreads();

    const int r0 = warp * 16;    // each warp owns 16 rows (edges)

    // ---- stage 2: e2 = relu(e1 @ k2_w + k2_b) ----
    {
        float acc[16][4];
        #pragma unroll
        for (int nt = 0; nt < 16; nt++)
            acc[nt][0] = acc[nt][1] = acc[nt][2] = acc[nt][3] = 0.f;

        #pragma unroll
        for (int ks = 0; ks < 8; ks++) {
            int k0 = ks * 16 + tg * 2;
            uint32_t a0 = *(const uint32_t*)&Ah[(r0 + g    ) * ST + k0];
            uint32_t a1 = *(const uint32_t*)&Ah[(r0 + g + 8) * ST + k0];
            uint32_t a2 = *(const uint32_t*)&Ah[(r0 + g    ) * ST + k0 + 8];
            uint32_t a3 = *(const uint32_t*)&Ah[(r0 + g + 8) * ST + k0 + 8];
            #pragma unroll
            for (int nt = 0; nt < 16; nt++) {
                uint32_t b0 = *(const uint32_t*)&Bh[(nt * 8 + g) * ST + k0];
                uint32_t b1 = *(const uint32_t*)&Bh[(nt * 8 + g) * ST + k0 + 8];
                mma16816(acc[nt], a0, a1, a2, a3, b0, b1);
            }
        }
        // relu + bias, write e2 back over A as half2 (warp-private rows)
        #pragma unroll
        for (int nt = 0; nt < 16; nt++) {
            #pragma unroll
            for (int qr = 0; qr < 2; qr++) {
                int row = r0 + g + qr * 8;
                int col = nt * 8 + tg * 2;
                __half2 hv = __floats2half2_rn(
                    fmaxf(acc[nt][qr * 2 + 0] + k2b[col], 0.f),
                    fmaxf(acc[nt][qr * 2 + 1] + k2b[col + 1], 0.f));
                *(__half2*)&Ah[row * ST + col] = hv;
            }
        }
    }

    // ---- stage 3: W = e2 @ k3_w + k3_b (two 128-col halves) -> fp16 global ----
    for (int half = 0; half < 2; half++) {
        __syncthreads();
        for (int i = tid; i < KW * KW; i += 256) {
            int n = i >> 7, k = i & 127;
            Bh[n * ST + k] = d_k3h[(half * 128 + n) * KW + k];
        }
        __syncthreads();

        float acc[16][4];
        #pragma unroll
        for (int nt = 0; nt < 16; nt++)
            acc[nt][0] = acc[nt][1] = acc[nt][2] = acc[nt][3] = 0.f;

        #pragma unroll
        for (int ks = 0; ks < 8; ks++) {
            int k0 = ks * 16 + tg * 2;
            uint32_t a0 = *(const uint32_t*)&Ah[(r0 + g    ) * ST + k0];
            uint32_t a1 = *(const uint32_t*)&Ah[(r0 + g + 8) * ST + k0];
            uint32_t a2 = *(const uint32_t*)&Ah[(r0 + g    ) * ST + k0 + 8];
            uint32_t a3 = *(const uint32_t*)&Ah[(r0 + g + 8) * ST + k0 + 8];
            #pragma unroll
            for (int nt = 0; nt < 16; nt++) {
                uint32_t b0 = *(const uint32_t*)&Bh[(nt * 8 + g) * ST + k0];
                uint32_t b1 = *(const uint32_t*)&Bh[(nt * 8 + g) * ST + k0 + 8];
                mma16816(acc[nt], a0, a1, a2, a3, b0, b1);
            }
        }
        // write W (fp16, half2-packed) to global
        __half2* Wg = (__half2*)d_W;
        #pragma unroll
        for (int nt = 0; nt < 16; nt++) {
            #pragma unroll
            for (int qr = 0; qr < 2; qr++) {
                int row = r0 + g + qr * 8;
                int col = half * 128 + nt * 8 + tg * 2;
                __half2 hv = __floats2half2_rn(
                    acc[nt][qr * 2 + 0] + k3b[col],
                    acc[nt][qr * 2 + 1] + k3b[col + 1]);
                Wg[(ebase + row) * 128 + (col >> 1)] = hv;
            }
        }
    }
}

// msg = h[src] @ W_e ; atomic scatter-add into agg[dst]
__global__ void k_conv(const void* __restrict__ ei, const float* __restrict__ hin)
{
    long long e = (long long)blockIdx.x * 8 + (threadIdx.x >> 4);
    int o = threadIdx.x & 15;
    if (e >= EE) return;
    long long src, dst;
    if (d_is64) {
        const long long* p = (const long long*)ei;
        src = p[e]; dst = p[EE + e];
    } else {
        const int* p = (const int*)ei;
        src = p[e]; dst = p[EE + e];
    }
    const float4* hr4 = (const float4*)(hin + src * EMB);
    float4 h0 = hr4[0], h1 = hr4[1], h2 = hr4[2], h3 = hr4[3];
    float hr[16] = {h0.x,h0.y,h0.z,h0.w, h1.x,h1.y,h1.z,h1.w,
                    h2.x,h2.y,h2.z,h2.w, h3.x,h3.y,h3.z,h3.w};
    const __half* Wr = d_W + e * 256;
    float m = 0.f;
    #pragma unroll
    for (int i = 0; i < 16; i++) m = fmaf(hr[i], __half2float(Wr[i * 16 + o]), m);
    atomicAdd(&d_agg[dst * EMB + o], m);
}

// h_out = relu(agg/denom + h_in @ root_w + conv_b); zero agg for next round
__global__ void k_update(const float* __restrict__ hin, float* __restrict__ hout,
                         const float* __restrict__ root_w, const float* __restrict__ conv_b)
{
    int t = blockIdx.x * blockDim.x + threadIdx.x;
    if (t >= NN * EMB) return;
    int n = t >> 4, o = t & 15;
    float denom = fmaxf(d_cnt[n], 1.f);
    float v = d_agg[t] / denom;
    const float* hr = hin + n * EMB;
    #pragma unroll
    for (int i = 0; i < 16; i++) v = fmaf(hr[i], root_w[i * EMB + o], v);
    v += conv_b[o];
    hout[t] = fmaxf(v, 0.f);
    d_agg[t] = 0.f;
}

__global__ void k_out(const float* __restrict__ hin,
                      const float* __restrict__ inv_w, const float* __restrict__ inv_b,
                      float* __restrict__ out)
{
    int t = blockIdx.x * blockDim.x + threadIdx.x;
    if (t >= NN * 3) return;
    int n = t / 3, f = t % 3;
    float v = inv_b[f];
    const float* hr = hin + n * EMB;
    #pragma unroll
    for (int i = 0; i < 16; i++) v = fmaf(hr[i], inv_w[i * 3 + f], v);
    out[t] = v;
}

// ---------------- launcher ----------------
extern "C" void kernel_launch(void* const* d_in, const int* in_sizes, int n_in,
                              void* d_out, int out_size)
{
    const float* x      = (const float*)d_in[0];
    const void*  ei     = d_in[1];
    const float* ea     = (const float*)d_in[2];
    const float* emb_w  = (const float*)d_in[3];
    const float* emb_b  = (const float*)d_in[4];
    const float* k1_w   = (const float*)d_in[5];
    const float* k1_b   = (const float*)d_in[6];
    const float* k2_w   = (const float*)d_in[7];
    const float* k2_b   = (const float*)d_in[8];
    const float* k3_w   = (const float*)d_in[9];
    const float* k3_b   = (const float*)d_in[10];
    const float* root_w = (const float*)d_in[11];
    const float* conv_b = (const float*)d_in[12];
    const float* inv_w  = (const float*)d_in[13];
    const float* inv_b  = (const float*)d_in[14];
    float* out = (float*)d_out;

    const int ST = KW + 8;
    const int smemBytes = 2 * 128 * ST * (int)sizeof(__half);   // 69632
    cudaFuncSetAttribute(k_mlp, cudaFuncAttributeMaxDynamicSharedMemorySize, smemBytes);

    static float* hA = nullptr;
    static float* hB = nullptr;
    if (!hA) {
        cudaGetSymbolAddress((void**)&hA, d_hA);
        cudaGetSymbolAddress((void**)&hB, d_hB);
    }

    k_detect<<<1, 256>>>((const int*)ei);
    k_prep<<<(KW * KW + 256 * KW + 255) / 256, 256>>>(k2_w, k3_w);
    k_init<<<(NN * EMB + 255) / 256, 256>>>(x, emb_w, emb_b);
    k_cnt<<<(EE + 255) / 256, 256>>>(ei);
    k_mlp<<<EE / 128, 256, smemBytes>>>(ea, k1_w, k1_b, k2_b, k3_b);

    float* hin  = hA;
    float* hout = hB;
    for (int it = 0; it < NCONV; it++) {
        k_conv<<<EE / 8, 128>>>(ei, hin);
        k_update<<<(NN * EMB + 255) / 256, 256>>>(hin, hout, root_w, conv_b);
        float* tmp = hin; hin = hout; hout = tmp;
    }
    k_out<<<(NN * 3 + 255) / 256, 256>>>(hin, inv_w, inv_b, out);
}

// round 3
// speedup vs baseline: 2.1098x; 1.1094x over previous
#include <cuda_runtime.h>
#include <cuda_fp16.h>
#include <cstdint>

#define NN   50000
#define EE   800000
#define EMB  16
#define KW   128
#define NCONV 4

// ---------------- device scratch (no cudaMalloc allowed) ----------------
__device__ __half d_W[(size_t)EE * 256];      // per-edge 16x16 weight matrices (fp16)
__device__ float  d_hA[NN * EMB];
__device__ float  d_hB[NN * EMB];
__device__ float  d_agg[NN * EMB];
__device__ float  d_cnt[NN];
__device__ __half d_k2h[KW * KW];             // k2_w transposed [n][k]
__device__ __half d_k3h[256 * KW];            // k3_w transposed [n][k]
__device__ int    d_is64;

// ---------------- helpers ----------------
__device__ __forceinline__ void mma16816(float* c,
    uint32_t a0, uint32_t a1, uint32_t a2, uint32_t a3,
    uint32_t b0, uint32_t b1)
{
    asm volatile(
        "mma.sync.aligned.m16n8k16.row.col.f32.f16.f16.f32 "
        "{%0,%1,%2,%3},{%4,%5,%6,%7},{%8,%9},{%0,%1,%2,%3};\n"
        : "+f"(c[0]), "+f"(c[1]), "+f"(c[2]), "+f"(c[3])
        : "r"(a0), "r"(a1), "r"(a2), "r"(a3), "r"(b0), "r"(b1));
}

__device__ __forceinline__ void ldsm_x4(uint32_t* a, uint32_t saddr)
{
    asm volatile(
        "ldmatrix.sync.aligned.m8n8.x4.shared.b16 {%0,%1,%2,%3}, [%4];\n"
        : "=r"(a[0]), "=r"(a[1]), "=r"(a[2]), "=r"(a[3]) : "r"(saddr));
}

// ---------------- kernels ----------------

__global__ void k_detect(const int* __restrict__ ei)
{
    __shared__ int anynz;
    if (threadIdx.x == 0) anynz = 0;
    __syncthreads();
    int v = ei[2 * threadIdx.x + 1];
    if (v != 0) atomicOr(&anynz, 1);
    __syncthreads();
    if (threadIdx.x == 0) d_is64 = (anynz == 0) ? 1 : 0;
}

// Transpose + fp16-convert k2/k3 weights once per launch.
__global__ void k_prep(const float* __restrict__ k2w, const float* __restrict__ k3w)
{
    int t = blockIdx.x * blockDim.x + threadIdx.x;
    if (t < KW * KW) {
        int n = t >> 7, k = t & 127;
        d_k2h[t] = __float2half_rn(k2w[k * KW + n]);
    } else if (t < KW * KW + 256 * KW) {
        int t2 = t - KW * KW;
        int n = t2 >> 7, k = t2 & 127;
        d_k3h[t2] = __float2half_rn(k3w[k * 256 + n]);
    }
}

// h0 = x @ emb_w + emb_b ; zero agg & counts
__global__ void k_init(const float* __restrict__ x,
                       const float* __restrict__ emb_w,
                       const float* __restrict__ emb_b)
{
    int t = blockIdx.x * blockDim.x + threadIdx.x;
    if (t >= NN * EMB) return;
    int n = t >> 4, o = t & 15;
    float v = emb_b[o];
    #pragma unroll
    for (int f = 0; f < 3; f++) v += x[n * 3 + f] * emb_w[f * EMB + o];
    d_hA[t]  = v;
    d_agg[t] = 0.f;
    if (o == 0) d_cnt[n] = 0.f;
}

__global__ void k_cnt(const void* __restrict__ ei)
{
    long long e = (long long)blockIdx.x * blockDim.x + threadIdx.x;
    if (e >= EE) return;
    long long dst;
    if (d_is64) dst = ((const long long*)ei)[EE + e];
    else        dst = ((const int*)ei)[EE + e];
    atomicAdd(&d_cnt[dst], 1.f);
}

// Fused edge-MLP: 128 edges/block, warp-per-N-columns, B in registers,
// A via ldmatrix from smem.
__global__ __launch_bounds__(256) void k_mlp(
    const float* __restrict__ ea,
    const float* __restrict__ k1w, const float* __restrict__ k1b,
    const float* __restrict__ k2b, const float* __restrict__ k3b)
{
    const int ST = KW + 8;                 // smem row stride in halves
    extern __shared__ __half sm[];
    __half* A1 = sm;                       // e1: 128 x ST
    __half* A2 = A1 + 128 * ST;            // e2: 128 x ST

    const int tid  = threadIdx.x;
    const int warp = tid >> 5;
    const int lane = tid & 31;
    const int g    = lane >> 2;
    const int tg   = lane & 3;
    const long long ebase = (long long)blockIdx.x * 128;

    const uint32_t sA1 = (uint32_t)__cvta_generic_to_shared(A1);
    const uint32_t sA2 = (uint32_t)__cvta_generic_to_shared(A2);

    // ---- stage 1: e1 = relu(ea @ k1_w + k1_b) -> fp16 smem ----
    {
        int r  = tid >> 1;
        int j0 = (tid & 1) * 64;
        float a[6];
        const float* earow = ea + (ebase + r) * 6;
        #pragma unroll
        for (int f = 0; f < 6; f++) a[f] = earow[f];
        #pragma unroll 8
        for (int jj = 0; jj < 64; jj++) {
            int j = j0 + jj;
            float v = k1b[j];
            #pragma unroll
            for (int f = 0; f < 6; f++) v = fmaf(a[f], k1w[f * KW + j], v);
            A1[r * ST + j] = __float2half_rn(fmaxf(v, 0.f));
        }
    }
    __syncthreads();

    // ---- stage 2: e2 = relu(e1 @ k2_w + k2_b) ----
    // warp owns cols [warp*16, warp*16+16); B frags in registers from global.
    {
        const int c0 = warp * 16;
        uint32_t B2[2][8][2];
        #pragma unroll
        for (int nt = 0; nt < 2; nt++) {
            const __half* brow = d_k2h + (c0 + nt * 8 + g) * KW;
            #pragma unroll
            for (int ks = 0; ks < 8; ks++) {
                B2[nt][ks][0] = *(const uint32_t*)&brow[ks * 16 + tg * 2];
                B2[nt][ks][1] = *(const uint32_t*)&brow[ks * 16 + 8 + tg * 2];
            }
        }
        float bias0 = k2b[c0 + tg * 2],     bias1 = k2b[c0 + tg * 2 + 1];
        float bias2 = k2b[c0 + 8 + tg * 2], bias3 = k2b[c0 + 8 + tg * 2 + 1];

        #pragma unroll
        for (int rt = 0; rt < 8; rt++) {
            const int r0 = rt * 16;
            float acc[2][4];
            #pragma unroll
            for (int nt = 0; nt < 2; nt++)
                acc[nt][0] = acc[nt][1] = acc[nt][2] = acc[nt][3] = 0.f;
            #pragma unroll
            for (int ks = 0; ks < 8; ks++) {
                uint32_t a[4];
                uint32_t addr = sA1 + ((r0 + (lane & 15)) * ST + ks * 16 + (lane >> 4) * 8) * 2;
                ldsm_x4(a, addr);
                mma16816(acc[0], a[0], a[1], a[2], a[3], B2[0][ks][0], B2[0][ks][1]);
                mma16816(acc[1], a[0], a[1], a[2], a[3], B2[1][ks][0], B2[1][ks][1]);
            }
            // relu+bias -> A2 (half2)
            #pragma unroll
            for (int nt = 0; nt < 2; nt++) {
                float ba = (nt == 0) ? bias0 : bias2;
                float bb = (nt == 0) ? bias1 : bias3;
                int col = c0 + nt * 8 + tg * 2;
                *(__half2*)&A2[(r0 + g) * ST + col] = __floats2half2_rn(
                    fmaxf(acc[nt][0] + ba, 0.f), fmaxf(acc[nt][1] + bb, 0.f));
                *(__half2*)&A2[(r0 + g + 8) * ST + col] = __floats2half2_rn(
                    fmaxf(acc[nt][2] + ba, 0.f), fmaxf(acc[nt][3] + bb, 0.f));
            }
        }
    }
    __syncthreads();

    // ---- stage 3: W = e2 @ k3_w + k3_b -> fp16 global ----
    // warp owns cols [warp*32, warp*32+32)
    {
        const int c0 = warp * 32;
        uint32_t B3[4][8][2];
        #pragma unroll
        for (int nt = 0; nt < 4; nt++) {
            const __half* brow = d_k3h + (c0 + nt * 8 + g) * KW;
            #pragma unroll
            for (int ks = 0; ks < 8; ks++) {
                B3[nt][ks][0] = *(const uint32_t*)&brow[ks * 16 + tg * 2];
                B3[nt][ks][1] = *(const uint32_t*)&brow[ks * 16 + 8 + tg * 2];
            }
        }
        float biasA[4], biasB[4];
        #pragma unroll
        for (int nt = 0; nt < 4; nt++) {
            biasA[nt] = k3b[c0 + nt * 8 + tg * 2];
            biasB[nt] = k3b[c0 + nt * 8 + tg * 2 + 1];
        }

        __half2* Wg = (__half2*)d_W;
        #pragma unroll
        for (int rt = 0; rt < 8; rt++) {
            const int r0 = rt * 16;
            float acc[4][4];
            #pragma unroll
            for (int nt = 0; nt < 4; nt++)
                acc[nt][0] = acc[nt][1] = acc[nt][2] = acc[nt][3] = 0.f;
            #pragma unroll
            for (int ks = 0; ks < 8; ks++) {
                uint32_t a[4];
                uint32_t addr = sA2 + ((r0 + (lane & 15)) * ST + ks * 16 + (lane >> 4) * 8) * 2;
                ldsm_x4(a, addr);
                #pragma unroll
                for (int nt = 0; nt < 4; nt++)
                    mma16816(acc[nt], a[0], a[1], a[2], a[3], B3[nt][ks][0], B3[nt][ks][1]);
            }
            #pragma unroll
            for (int nt = 0; nt < 4; nt++) {
                int col = c0 + nt * 8 + tg * 2;
                Wg[(ebase + r0 + g) * 128 + (col >> 1)] = __floats2half2_rn(
                    acc[nt][0] + biasA[nt], acc[nt][1] + biasB[nt]);
                Wg[(ebase + r0 + g + 8) * 128 + (col >> 1)] = __floats2half2_rn(
                    acc[nt][2] + biasA[nt], acc[nt][3] + biasB[nt]);
            }
        }
    }
}

// msg = h[src] @ W_e ; vector scatter-add into agg[dst]
__global__ void k_conv(const void* __restrict__ ei, const float* __restrict__ hin)
{
    long long e = (long long)blockIdx.x * 32 + (threadIdx.x >> 3);
    int o = threadIdx.x & 7;           // output half2 index (cols 2o, 2o+1)
    if (e >= EE) return;
    long long src, dst;
    if (d_is64) {
        const long long* p = (const long long*)ei;
        src = p[e]; dst = p[EE + e];
    } else {
        const int* p = (const int*)ei;
        src = p[e]; dst = p[EE + e];
    }
    const float4* hr4 = (const float4*)(hin + src * EMB);
    float4 h0 = hr4[0], h1 = hr4[1], h2 = hr4[2], h3 = hr4[3];
    float hr[16] = {h0.x,h0.y,h0.z,h0.w, h1.x,h1.y,h1.z,h1.w,
                    h2.x,h2.y,h2.z,h2.w, h3.x,h3.y,h3.z,h3.w};
    const __half2* Wr = (const __half2*)(d_W + e * 256);
    float mx = 0.f, my = 0.f;
    #pragma unroll
    for (int i = 0; i < 16; i++) {
        float2 wf = __half22float2(Wr[i * 8 + o]);
        mx = fmaf(hr[i], wf.x, mx);
        my = fmaf(hr[i], wf.y, my);
    }
    float* dp = &d_agg[dst * EMB + 2 * o];
    asm volatile("red.global.add.v2.f32 [%0], {%1,%2};\n"
                 :: "l"(dp), "f"(mx), "f"(my) : "memory");
}

// h_out = relu(agg/denom + h_in @ root_w + conv_b); zero agg for next round
__global__ void k_update(const float* __restrict__ hin, float* __restrict__ hout,
                         const float* __restrict__ root_w, const float* __restrict__ conv_b)
{
    int t = blockIdx.x * blockDim.x + threadIdx.x;
    if (t >= NN * EMB) return;
    int n = t >> 4, o = t & 15;
    float denom = fmaxf(d_cnt[n], 1.f);
    float v = d_agg[t] / denom;
    const float* hr = hin + n * EMB;
    #pragma unroll
    for (int i = 0; i < 16; i++) v = fmaf(hr[i], root_w[i * EMB + o], v);
    v += conv_b[o];
    hout[t] = fmaxf(v, 0.f);
    d_agg[t] = 0.f;
}

__global__ void k_out(const float* __restrict__ hin,
                      const float* __restrict__ inv_w, const float* __restrict__ inv_b,
                      float* __restrict__ out)
{
    int t = blockIdx.x * blockDim.x + threadIdx.x;
    if (t >= NN * 3) return;
    int n = t / 3, f = t % 3;
    float v = inv_b[f];
    const float* hr = hin + n * EMB;
    #pragma unroll
    for (int i = 0; i < 16; i++) v = fmaf(hr[i], inv_w[i * 3 + f], v);
    out[t] = v;
}

// ---------------- launcher ----------------
extern "C" void kernel_launch(void* const* d_in, const int* in_sizes, int n_in,
                              void* d_out, int out_size)
{
    const float* x      = (const float*)d_in[0];
    const void*  ei     = d_in[1];
    const float* ea     = (const float*)d_in[2];
    const float* emb_w  = (const float*)d_in[3];
    const float* emb_b  = (const float*)d_in[4];
    const float* k1_w   = (const float*)d_in[5];
    const float* k1_b   = (const float*)d_in[6];
    const float* k2_w   = (const float*)d_in[7];
    const float* k2_b   = (const float*)d_in[8];
    const float* k3_w   = (const float*)d_in[9];
    const float* k3_b   = (const float*)d_in[10];
    const float* root_w = (const float*)d_in[11];
    const float* conv_b = (const float*)d_in[12];
    const float* inv_w  = (const float*)d_in[13];
    const float* inv_b  = (const float*)d_in[14];
    float* out = (float*)d_out;

    const int ST = KW + 8;
    const int smemBytes = 2 * 128 * ST * (int)sizeof(__half);   // 69632
    cudaFuncSetAttribute(k_mlp, cudaFuncAttributeMaxDynamicSharedMemorySize, smemBytes);

    static float* hA = nullptr;
    static float* hB = nullptr;
    if (!hA) {
        cudaGetSymbolAddress((void**)&hA, d_hA);
        cudaGetSymbolAddress((void**)&hB, d_hB);
    }

    k_detect<<<1, 256>>>((const int*)ei);
    k_prep<<<(KW * KW + 256 * KW + 255) / 256, 256>>>(k2_w, k3_w);
    k_init<<<(NN * EMB + 255) / 256, 256>>>(x, emb_w, emb_b);
    k_cnt<<<(EE + 255) / 256, 256>>>(ei);
    k_mlp<<<EE / 128, 256, smemBytes>>>(ea, k1_w, k1_b, k2_b, k3_b);

    float* hin  = hA;
    float* hout = hB;
    for (int it = 0; it < NCONV; it++) {
        k_conv<<<EE / 32, 256>>>(ei, hin);
        k_update<<<(NN * EMB + 255) / 256, 256>>>(hin, hout, root_w, conv_b);
        float* tmp = hin; hin = hout; hout = tmp;
    }
    k_out<<<(NN * 3 + 255) / 256, 256>>>(hin, inv_w, inv_b, out);
}

// round 5
// speedup vs baseline: 2.1673x; 1.0273x over previous
#include <cuda_runtime.h>
#include <cuda_fp16.h>
#include <cstdint>

#define NN   50000
#define EE   800000
#define EMB  16
#define KW   128
#define NCONV 4

// ---------------- device scratch (no cudaMalloc allowed) ----------------
__device__ __half d_W[(size_t)EE * 256];      // per-edge 16x16 weight matrices (fp16)
__device__ float  d_hA[NN * EMB];
__device__ float  d_hB[NN * EMB];
__device__ float  d_agg[NN * EMB];
__device__ float  d_cnt[NN];
__device__ __half d_k2h[KW * KW];             // k2_w transposed [n][k]
__device__ __half d_k3h[256 * KW];            // k3_w transposed [n][k]
__device__ int    d_is64;

// ---------------- helpers ----------------
__device__ __forceinline__ void mma16816(float* c,
    uint32_t a0, uint32_t a1, uint32_t a2, uint32_t a3,
    uint32_t b0, uint32_t b1)
{
    asm volatile(
        "mma.sync.aligned.m16n8k16.row.col.f32.f16.f16.f32 "
        "{%0,%1,%2,%3},{%4,%5,%6,%7},{%8,%9},{%0,%1,%2,%3};\n"
        : "+f"(c[0]), "+f"(c[1]), "+f"(c[2]), "+f"(c[3])
        : "r"(a0), "r"(a1), "r"(a2), "r"(a3), "r"(b0), "r"(b1));
}

__device__ __forceinline__ void ldsm_x4(uint32_t* a, uint32_t saddr)
{
    asm volatile(
        "ldmatrix.sync.aligned.m8n8.x4.shared.b16 {%0,%1,%2,%3}, [%4];\n"
        : "=r"(a[0]), "=r"(a[1]), "=r"(a[2]), "=r"(a[3]) : "r"(saddr));
}

__device__ __forceinline__ void stcs_u32(void* p, uint32_t v)
{
    asm volatile("st.global.cs.b32 [%0], %1;\n" :: "l"(p), "r"(v) : "memory");
}

// ---------------- kernels ----------------

__global__ void k_detect(const int* __restrict__ ei)
{
    __shared__ int anynz;
    if (threadIdx.x == 0) anynz = 0;
    __syncthreads();
    int v = ei[2 * threadIdx.x + 1];
    if (v != 0) atomicOr(&anynz, 1);
    __syncthreads();
    if (threadIdx.x == 0) d_is64 = (anynz == 0) ? 1 : 0;
}

// Transpose + fp16-convert k2/k3 weights once per launch.
__global__ void k_prep(const float* __restrict__ k2w, const float* __restrict__ k3w)
{
    int t = blockIdx.x * blockDim.x + threadIdx.x;
    if (t < KW * KW) {
        int n = t >> 7, k = t & 127;
        d_k2h[t] = __float2half_rn(k2w[k * KW + n]);
    } else if (t < KW * KW + 256 * KW) {
        int t2 = t - KW * KW;
        int n = t2 >> 7, k = t2 & 127;
        d_k3h[t2] = __float2half_rn(k3w[k * 256 + n]);
    }
}

// h0 = x @ emb_w + emb_b ; zero agg & counts
__global__ void k_init(const float* __restrict__ x,
                       const float* __restrict__ emb_w,
                       const float* __restrict__ emb_b)
{
    int t = blockIdx.x * blockDim.x + threadIdx.x;
    if (t >= NN * EMB) return;
    int n = t >> 4, o = t & 15;
    float v = emb_b[o];
    #pragma unroll
    for (int f = 0; f < 3; f++) v += x[n * 3 + f] * emb_w[f * EMB + o];
    d_hA[t]  = v;
    d_agg[t] = 0.f;
    if (o == 0) d_cnt[n] = 0.f;
}

__global__ void k_cnt(const void* __restrict__ ei)
{
    long long e = (long long)blockIdx.x * blockDim.x + threadIdx.x;
    if (e >= EE) return;
    long long dst;
    if (d_is64) dst = ((const long long*)ei)[EE + e];
    else        dst = ((const int*)ei)[EE + e];
    atomicAdd(&d_cnt[dst], 1.f);
}

// Fused edge-MLP: 128 edges/block, warp-per-N-columns, B in registers,
// A via double-buffered ldmatrix from smem.
__global__ __launch_bounds__(256) void k_mlp(
    const float* __restrict__ ea,
    const float* __restrict__ k1w, const float* __restrict__ k1b,
    const float* __restrict__ k2b, const float* __restrict__ k3b)
{
    const int ST = KW + 8;                 // smem row stride in halves
    extern __shared__ __half sm[];
    __half* A1 = sm;                       // e1: 128 x ST
    __half* A2 = A1 + 128 * ST;            // e2: 128 x ST

    const int tid  = threadIdx.x;
    const int warp = tid >> 5;
    const int lane = tid & 31;
    const int g    = lane >> 2;
    const int tg   = lane & 3;
    const long long ebase = (long long)blockIdx.x * 128;

    const uint32_t sA1 = (uint32_t)__cvta_generic_to_shared(A1);
    const uint32_t sA2 = (uint32_t)__cvta_generic_to_shared(A2);
    const uint32_t lrow = (lane & 15);
    const uint32_t lcol = (lane >> 4) * 8;

    // ---- stage 1: e1 = relu(ea @ k1_w + k1_b) -> fp16 smem ----
    {
        int r  = tid >> 1;
        int j0 = (tid & 1) * 64;
        float a[6];
        const float* earow = ea + (ebase + r) * 6;
        #pragma unroll
        for (int f = 0; f < 6; f++) a[f] = earow[f];
        #pragma unroll 8
        for (int jj = 0; jj < 64; jj++) {
            int j = j0 + jj;
            float v = k1b[j];
            #pragma unroll
            for (int f = 0; f < 6; f++) v = fmaf(a[f], k1w[f * KW + j], v);
            A1[r * ST + j] = __float2half_rn(fmaxf(v, 0.f));
        }
    }
    __syncthreads();

    // ---- stage 2: e2 = relu(e1 @ k2_w + k2_b) ----
    {
        const int c0 = warp * 16;
        uint32_t B2[2][8][2];
        #pragma unroll
        for (int nt = 0; nt < 2; nt++) {
            const __half* brow = d_k2h + (c0 + nt * 8 + g) * KW;
            #pragma unroll
            for (int ks = 0; ks < 8; ks++) {
                B2[nt][ks][0] = *(const uint32_t*)&brow[ks * 16 + tg * 2];
                B2[nt][ks][1] = *(const uint32_t*)&brow[ks * 16 + 8 + tg * 2];
            }
        }
        float bias0 = k2b[c0 + tg * 2],     bias1 = k2b[c0 + tg * 2 + 1];
        float bias2 = k2b[c0 + 8 + tg * 2], bias3 = k2b[c0 + 8 + tg * 2 + 1];

        #pragma unroll
        for (int rt = 0; rt < 8; rt++) {
            const int r0 = rt * 16;
            float acc[2][4];
            #pragma unroll
            for (int nt = 0; nt < 2; nt++)
                acc[nt][0] = acc[nt][1] = acc[nt][2] = acc[nt][3] = 0.f;

            uint32_t acur[4], anxt[4];
            ldsm_x4(acur, sA1 + ((r0 + lrow) * ST + lcol) * 2);
            #pragma unroll
            for (int ks = 0; ks < 8; ks++) {
                if (ks < 7)
                    ldsm_x4(anxt, sA1 + ((r0 + lrow) * ST + (ks + 1) * 16 + lcol) * 2);
                mma16816(acc[0], acur[0], acur[1], acur[2], acur[3], B2[0][ks][0], B2[0][ks][1]);
                mma16816(acc[1], acur[0], acur[1], acur[2], acur[3], B2[1][ks][0], B2[1][ks][1]);
                #pragma unroll
                for (int q = 0; q < 4; q++) acur[q] = anxt[q];
            }
            #pragma unroll
            for (int nt = 0; nt < 2; nt++) {
                float ba = (nt == 0) ? bias0 : bias2;
                float bb = (nt == 0) ? bias1 : bias3;
                int col = c0 + nt * 8 + tg * 2;
                *(__half2*)&A2[(r0 + g) * ST + col] = __floats2half2_rn(
                    fmaxf(acc[nt][0] + ba, 0.f), fmaxf(acc[nt][1] + bb, 0.f));
                *(__half2*)&A2[(r0 + g + 8) * ST + col] = __floats2half2_rn(
                    fmaxf(acc[nt][2] + ba, 0.f), fmaxf(acc[nt][3] + bb, 0.f));
            }
        }
    }
    __syncthreads();

    // ---- stage 3: W = e2 @ k3_w + k3_b -> fp16 global (streaming stores) ----
    {
        const int c0 = warp * 32;
        uint32_t B3[4][8][2];
        #pragma unroll
        for (int nt = 0; nt < 4; nt++) {
            const __half* brow = d_k3h + (c0 + nt * 8 + g) * KW;
            #pragma unroll
            for (int ks = 0; ks < 8; ks++) {
                B3[nt][ks][0] = *(const uint32_t*)&brow[ks * 16 + tg * 2];
                B3[nt][ks][1] = *(const uint32_t*)&brow[ks * 16 + 8 + tg * 2];
            }
        }
        float biasA[4], biasB[4];
        #pragma unroll
        for (int nt = 0; nt < 4; nt++) {
            biasA[nt] = k3b[c0 + nt * 8 + tg * 2];
            biasB[nt] = k3b[c0 + nt * 8 + tg * 2 + 1];
        }

        __half2* Wg = (__half2*)d_W;
        #pragma unroll
        for (int rt = 0; rt < 8; rt++) {
            const int r0 = rt * 16;
            float acc[4][4];
            #pragma unroll
            for (int nt = 0; nt < 4; nt++)
                acc[nt][0] = acc[nt][1] = acc[nt][2] = acc[nt][3] = 0.f;

            uint32_t acur[4], anxt[4];
            ldsm_x4(acur, sA2 + ((r0 + lrow) * ST + lcol) * 2);
            #pragma unroll
            for (int ks = 0; ks < 8; ks++) {
                if (ks < 7)
                    ldsm_x4(anxt, sA2 + ((r0 + lrow) * ST + (ks + 1) * 16 + lcol) * 2);
                #pragma unroll
                for (int nt = 0; nt < 4; nt++)
                    mma16816(acc[nt], acur[0], acur[1], acur[2], acur[3],
                             B3[nt][ks][0], B3[nt][ks][1]);
                #pragma unroll
                for (int q = 0; q < 4; q++) acur[q] = anxt[q];
            }
            #pragma unroll
            for (int nt = 0; nt < 4; nt++) {
                int col = c0 + nt * 8 + tg * 2;
                __half2 h0 = __floats2half2_rn(acc[nt][0] + biasA[nt], acc[nt][1] + biasB[nt]);
                __half2 h1 = __floats2half2_rn(acc[nt][2] + biasA[nt], acc[nt][3] + biasB[nt]);
                stcs_u32(&Wg[(ebase + r0 + g) * 128 + (col >> 1)], *(uint32_t*)&h0);
                stcs_u32(&Wg[(ebase + r0 + g + 8) * 128 + (col >> 1)], *(uint32_t*)&h1);
            }
        }
    }
}

// msg = h[src] @ W_e ; vector scatter-add into agg[dst]
__global__ void k_conv(const void* __restrict__ ei, const float* __restrict__ hin)
{
    long long e = (long long)blockIdx.x * 32 + (threadIdx.x >> 3);
    int o = threadIdx.x & 7;           // output half2 index (cols 2o, 2o+1)
    if (e >= EE) return;
    long long src, dst;
    if (d_is64) {
        const long long* p = (const long long*)ei;
        src = p[e]; dst = p[EE + e];
    } else {
        const int* p = (const int*)ei;
        src = p[e]; dst = p[EE + e];
    }
    const float4* hr4 = (const float4*)(hin + src * EMB);
    float4 h0 = hr4[0], h1 = hr4[1], h2 = hr4[2], h3 = hr4[3];
    float hr[16] = {h0.x,h0.y,h0.z,h0.w, h1.x,h1.y,h1.z,h1.w,
                    h2.x,h2.y,h2.z,h2.w, h3.x,h3.y,h3.z,h3.w};
    const __half2* Wr = (const __half2*)(d_W + e * 256);
    float mx = 0.f, my = 0.f;
    #pragma unroll
    for (int i = 0; i < 16; i++) {
        float2 wf = __half22float2(__ldcs(&Wr[i * 8 + o]));
        mx = fmaf(hr[i], wf.x, mx);
        my = fmaf(hr[i], wf.y, my);
    }
    float* dp = &d_agg[dst * EMB + 2 * o];
    asm volatile("red.global.add.v2.f32 [%0], {%1,%2};\n"
                 :: "l"(dp), "f"(mx), "f"(my) : "memory");
}

// h_out = relu(agg/denom + h_in @ root_w + conv_b); zero agg for next round
__global__ void k_update(const float* __restrict__ hin, float* __restrict__ hout,
                         const float* __restrict__ root_w, const float* __restrict__ conv_b)
{
    int t = blockIdx.x * blockDim.x + threadIdx.x;
    if (t >= NN * EMB) return;
    int n = t >> 4, o = t & 15;
    float denom = fmaxf(d_cnt[n], 1.f);
    float v = d_agg[t] / denom;
    const float* hr = hin + n * EMB;
    #pragma unroll
    for (int i = 0; i < 16; i++) v = fmaf(hr[i], root_w[i * EMB + o], v);
    v += conv_b[o];
    hout[t] = fmaxf(v, 0.f);
    d_agg[t] = 0.f;
}

__global__ void k_out(const float* __restrict__ hin,
                      const float* __restrict__ inv_w, const float* __restrict__ inv_b,
                      float* __restrict__ out)
{
    int t = blockIdx.x * blockDim.x + threadIdx.x;
    if (t >= NN * 3) return;
    int n = t / 3, f = t % 3;
    float v = inv_b[f];
    const float* hr = hin + n * EMB;
    #pragma unroll
    for (int i = 0; i < 16; i++) v = fmaf(hr[i], inv_w[i * 3 + f], v);
    out[t] = v;
}

// ---------------- launcher ----------------
extern "C" void kernel_launch(void* const* d_in, const int* in_sizes, int n_in,
                              void* d_out, int out_size)
{
    const float* x      = (const float*)d_in[0];
    const void*  ei     = d_in[1];
    const float* ea     = (const float*)d_in[2];
    const float* emb_w  = (const float*)d_in[3];
    const float* emb_b  = (const float*)d_in[4];
    const float* k1_w   = (const float*)d_in[5];
    const float* k1_b   = (const float*)d_in[6];
    const float* k2_w   = (const float*)d_in[7];
    const float* k2_b   = (const float*)d_in[8];
    const float* k3_w   = (const float*)d_in[9];
    const float* k3_b   = (const float*)d_in[10];
    const float* root_w = (const float*)d_in[11];
    const float* conv_b = (const float*)d_in[12];
    const float* inv_w  = (const float*)d_in[13];
    const float* inv_b  = (const float*)d_in[14];
    float* out = (float*)d_out;

    const int ST = KW + 8;
    const int smemBytes = 2 * 128 * ST * (int)sizeof(__half);   // 69632
    cudaFuncSetAttribute(k_mlp, cudaFuncAttributeMaxDynamicSharedMemorySize, smemBytes);

    static float* hA = nullptr;
    static float* hB = nullptr;
    if (!hA) {
        cudaGetSymbolAddress((void**)&hA, d_hA);
        cudaGetSymbolAddress((void**)&hB, d_hB);
    }

    // NOTE: launch order chosen so k_mlp sits in the ncu-profiled slot
    // (previously occupied by k_cnt). k_cnt only needs to precede k_update.
    k_detect<<<1, 256>>>((const int*)ei);
    k_prep<<<(KW * KW + 256 * KW + 255) / 256, 256>>>(k2_w, k3_w);
    k_init<<<(NN * EMB + 255) / 256, 256>>>(x, emb_w, emb_b);
    k_mlp<<<EE / 128, 256, smemBytes>>>(ea, k1_w, k1_b, k2_b, k3_b);
    k_cnt<<<(EE + 255) / 256, 256>>>(ei);

    float* hin  = hA;
    float* hout = hB;
    for (int it = 0; it < NCONV; it++) {
        k_conv<<<EE / 32, 256>>>(ei, hin);
        k_update<<<(NN * EMB + 255) / 256, 256>>>(hin, hout, root_w, conv_b);
        float* tmp = hin; hin = hout; hout = tmp;
    }
    k_out<<<(NN * 3 + 255) / 256, 256>>>(hin, inv_w, inv_b, out);
}

// round 6
// speedup vs baseline: 2.6704x; 1.2321x over previous
#include <cuda_runtime.h>
#include <cuda_fp16.h>
#include <cstdint>

#define NN   50000
#define EE   800000
#define EMB  16
#define KW   128
#define NCONV 4

// ---------------- device scratch (no cudaMalloc allowed) ----------------
__device__ __half d_W[(size_t)EE * 256];      // per-edge 16x16 weight matrices (fp16)
__device__ float  d_hA[NN * EMB];
__device__ float  d_hB[NN * EMB];
__device__ float  d_agg[NN * EMB];
__device__ float  d_cnt[NN];
__device__ __half d_k2h[KW * KW];             // k2_w transposed [n][k]
__device__ __half d_k3h[256 * KW];            // k3_w transposed [n][k]
__device__ int    d_is64;

// ---------------- helpers ----------------
__device__ __forceinline__ void mma16816(float* c,
    uint32_t a0, uint32_t a1, uint32_t a2, uint32_t a3,
    uint32_t b0, uint32_t b1)
{
    asm volatile(
        "mma.sync.aligned.m16n8k16.row.col.f32.f16.f16.f32 "
        "{%0,%1,%2,%3},{%4,%5,%6,%7},{%8,%9},{%0,%1,%2,%3};\n"
        : "+f"(c[0]), "+f"(c[1]), "+f"(c[2]), "+f"(c[3])
        : "r"(a0), "r"(a1), "r"(a2), "r"(a3), "r"(b0), "r"(b1));
}

__device__ __forceinline__ void mma16808(float* c, uint32_t a0, uint32_t a1, uint32_t b0)
{
    asm volatile(
        "mma.sync.aligned.m16n8k8.row.col.f32.f16.f16.f32 "
        "{%0,%1,%2,%3},{%4,%5},{%6},{%0,%1,%2,%3};\n"
        : "+f"(c[0]), "+f"(c[1]), "+f"(c[2]), "+f"(c[3])
        : "r"(a0), "r"(a1), "r"(b0));
}

__device__ __forceinline__ void ldsm_x4(uint32_t* a, uint32_t saddr)
{
    asm volatile(
        "ldmatrix.sync.aligned.m8n8.x4.shared.b16 {%0,%1,%2,%3}, [%4];\n"
        : "=r"(a[0]), "=r"(a[1]), "=r"(a[2]), "=r"(a[3]) : "r"(saddr));
}

__device__ __forceinline__ void ldsm_x2(uint32_t* a, uint32_t saddr)
{
    asm volatile(
        "ldmatrix.sync.aligned.m8n8.x2.shared.b16 {%0,%1}, [%2];\n"
        : "=r"(a[0]), "=r"(a[1]) : "r"(saddr));
}

__device__ __forceinline__ void stcs_u32(void* p, uint32_t v)
{
    asm volatile("st.global.cs.b32 [%0], %1;\n" :: "l"(p), "r"(v) : "memory");
}

// ---------------- kernels ----------------

__global__ void k_detect(const int* __restrict__ ei)
{
    __shared__ int anynz;
    if (threadIdx.x == 0) anynz = 0;
    __syncthreads();
    int v = ei[2 * threadIdx.x + 1];
    if (v != 0) atomicOr(&anynz, 1);
    __syncthreads();
    if (threadIdx.x == 0) d_is64 = (anynz == 0) ? 1 : 0;
}

// Transpose + fp16-convert k2/k3 weights once per launch.
__global__ void k_prep(const float* __restrict__ k2w, const float* __restrict__ k3w)
{
    int t = blockIdx.x * blockDim.x + threadIdx.x;
    if (t < KW * KW) {
        int n = t >> 7, k = t & 127;
        d_k2h[t] = __float2half_rn(k2w[k * KW + n]);
    } else if (t < KW * KW + 256 * KW) {
        int t2 = t - KW * KW;
        int n = t2 >> 7, k = t2 & 127;
        d_k3h[t2] = __float2half_rn(k3w[k * 256 + n]);
    }
}

// h0 = x @ emb_w + emb_b ; zero agg & counts
__global__ void k_init(const float* __restrict__ x,
                       const float* __restrict__ emb_w,
                       const float* __restrict__ emb_b)
{
    int t = blockIdx.x * blockDim.x + threadIdx.x;
    if (t >= NN * EMB) return;
    int n = t >> 4, o = t & 15;
    float v = emb_b[o];
    #pragma unroll
    for (int f = 0; f < 3; f++) v += x[n * 3 + f] * emb_w[f * EMB + o];
    d_hA[t]  = v;
    d_agg[t] = 0.f;
    if (o == 0) d_cnt[n] = 0.f;
}

__global__ void k_cnt(const void* __restrict__ ei)
{
    long long e = (long long)blockIdx.x * blockDim.x + threadIdx.x;
    if (e >= EE) return;
    long long dst;
    if (d_is64) dst = ((const long long*)ei)[EE + e];
    else        dst = ((const int*)ei)[EE + e];
    atomicAdd(&d_cnt[dst], 1.f);
}

// Fused edge-MLP: 128 edges/block. All three layers on tensor cores.
// Layer1: m16n8k8 (ea padded to k=8 fp16). Layers 2/3: m16n8k16,
// warp-per-N-columns with B fragments in registers.
__global__ __launch_bounds__(256, 2) void k_mlp(
    const float* __restrict__ ea,
    const float* __restrict__ k1w, const float* __restrict__ k1b,
    const float* __restrict__ k2b, const float* __restrict__ k3b)
{
    const int ST = KW + 8;                 // smem row stride in halves
    extern __shared__ __half sm[];
    __half* A1 = sm;                       // e1: 128 x ST
    __half* A2 = A1 + 128 * ST;            // e2: 128 x ST
    __half* EA = A2 + 128 * ST;            // ea fp16: 128 x 8

    const int tid  = threadIdx.x;
    const int warp = tid >> 5;
    const int lane = tid & 31;
    const int g    = lane >> 2;
    const int tg   = lane & 3;
    const long long ebase = (long long)blockIdx.x * 128;

    const uint32_t sA1 = (uint32_t)__cvta_generic_to_shared(A1);
    const uint32_t sA2 = (uint32_t)__cvta_generic_to_shared(A2);
    const uint32_t sEA = (uint32_t)__cvta_generic_to_shared(EA);
    const uint32_t lrow = (lane & 15);
    const uint32_t lcol = (lane >> 4) * 8;

    // ---- stage 0: ea -> fp16 smem tile [128 x 8] (k padded 6->8) ----
    if (tid < 128) {
        const float* er = ea + (ebase + tid) * 6;
        float a0 = er[0], a1 = er[1], a2 = er[2], a3 = er[3], a4 = er[4], a5 = er[5];
        __half2* row = (__half2*)(EA + tid * 8);
        row[0] = __floats2half2_rn(a0, a1);
        row[1] = __floats2half2_rn(a2, a3);
        row[2] = __floats2half2_rn(a4, a5);
        row[3] = __floats2half2_rn(0.f, 0.f);
    }

    // ---- stage 1: e1 = relu(ea @ k1_w + k1_b) via m16n8k8 ----
    {
        const int c0 = warp * 16;
        // B fragments: b[nt] = (k1w[k][n], k1w[k+1][n]) with k = tg*2, n = c0+nt*8+g
        uint32_t B1[2];
        #pragma unroll
        for (int nt = 0; nt < 2; nt++) {
            int n  = c0 + nt * 8 + g;
            int k0 = tg * 2;
            float f0 = (k0     < 6) ? k1w[k0 * KW + n]       : 0.f;
            float f1 = (k0 + 1 < 6) ? k1w[(k0 + 1) * KW + n] : 0.f;
            __half2 hv = __floats2half2_rn(f0, f1);
            B1[nt] = *(uint32_t*)&hv;
        }
        float bias0 = k1b[c0 + tg * 2],     bias1 = k1b[c0 + tg * 2 + 1];
        float bias2 = k1b[c0 + 8 + tg * 2], bias3 = k1b[c0 + 8 + tg * 2 + 1];
        __syncthreads();   // EA tile ready

        #pragma unroll
        for (int rt = 0; rt < 8; rt++) {
            uint32_t a[2];
            ldsm_x2(a, sEA + (uint32_t)(rt * 16 + lrow) * 16);
            float acc0[4] = {0.f, 0.f, 0.f, 0.f};
            float acc1[4] = {0.f, 0.f, 0.f, 0.f};
            mma16808(acc0, a[0], a[1], B1[0]);
            mma16808(acc1, a[0], a[1], B1[1]);
            int r0 = rt * 16;
            *(__half2*)&A1[(r0 + g) * ST + c0 + tg * 2] = __floats2half2_rn(
                fmaxf(acc0[0] + bias0, 0.f), fmaxf(acc0[1] + bias1, 0.f));
            *(__half2*)&A1[(r0 + g + 8) * ST + c0 + tg * 2] = __floats2half2_rn(
                fmaxf(acc0[2] + bias0, 0.f), fmaxf(acc0[3] + bias1, 0.f));
            *(__half2*)&A1[(r0 + g) * ST + c0 + 8 + tg * 2] = __floats2half2_rn(
                fmaxf(acc1[0] + bias2, 0.f), fmaxf(acc1[1] + bias3, 0.f));
            *(__half2*)&A1[(r0 + g + 8) * ST + c0 + 8 + tg * 2] = __floats2half2_rn(
                fmaxf(acc1[2] + bias2, 0.f), fmaxf(acc1[3] + bias3, 0.f));
        }
    }
    __syncthreads();

    // ---- stage 2: e2 = relu(e1 @ k2_w + k2_b) ----
    {
        const int c0 = warp * 16;
        uint32_t B2[2][8][2];
        #pragma unroll
        for (int nt = 0; nt < 2; nt++) {
            const __half* brow = d_k2h + (c0 + nt * 8 + g) * KW;
            #pragma unroll
            for (int ks = 0; ks < 8; ks++) {
                B2[nt][ks][0] = *(const uint32_t*)&brow[ks * 16 + tg * 2];
                B2[nt][ks][1] = *(const uint32_t*)&brow[ks * 16 + 8 + tg * 2];
            }
        }
        float bias0 = k2b[c0 + tg * 2],     bias1 = k2b[c0 + tg * 2 + 1];
        float bias2 = k2b[c0 + 8 + tg * 2], bias3 = k2b[c0 + 8 + tg * 2 + 1];

        #pragma unroll
        for (int rt = 0; rt < 8; rt++) {
            const int r0 = rt * 16;
            float acc[2][4];
            #pragma unroll
            for (int nt = 0; nt < 2; nt++)
                acc[nt][0] = acc[nt][1] = acc[nt][2] = acc[nt][3] = 0.f;
            #pragma unroll
            for (int ks = 0; ks < 8; ks++) {
                uint32_t a[4];
                ldsm_x4(a, sA1 + ((r0 + lrow) * ST + ks * 16 + lcol) * 2);
                mma16816(acc[0], a[0], a[1], a[2], a[3], B2[0][ks][0], B2[0][ks][1]);
                mma16816(acc[1], a[0], a[1], a[2], a[3], B2[1][ks][0], B2[1][ks][1]);
            }
            #pragma unroll
            for (int nt = 0; nt < 2; nt++) {
                float ba = (nt == 0) ? bias0 : bias2;
                float bb = (nt == 0) ? bias1 : bias3;
                int col = c0 + nt * 8 + tg * 2;
                *(__half2*)&A2[(r0 + g) * ST + col] = __floats2half2_rn(
                    fmaxf(acc[nt][0] + ba, 0.f), fmaxf(acc[nt][1] + bb, 0.f));
                *(__half2*)&A2[(r0 + g + 8) * ST + col] = __floats2half2_rn(
                    fmaxf(acc[nt][2] + ba, 0.f), fmaxf(acc[nt][3] + bb, 0.f));
            }
        }
    }
    __syncthreads();

    // ---- stage 3: W = e2 @ k3_w + k3_b -> fp16 global (streaming stores) ----
    {
        const int c0 = warp * 32;
        uint32_t B3[4][8][2];
        #pragma unroll
        for (int nt = 0; nt < 4; nt++) {
            const __half* brow = d_k3h + (c0 + nt * 8 + g) * KW;
            #pragma unroll
            for (int ks = 0; ks < 8; ks++) {
                B3[nt][ks][0] = *(const uint32_t*)&brow[ks * 16 + tg * 2];
                B3[nt][ks][1] = *(const uint32_t*)&brow[ks * 16 + 8 + tg * 2];
            }
        }
        float biasA[4], biasB[4];
        #pragma unroll
        for (int nt = 0; nt < 4; nt++) {
            biasA[nt] = k3b[c0 + nt * 8 + tg * 2];
            biasB[nt] = k3b[c0 + nt * 8 + tg * 2 + 1];
        }

        __half2* Wg = (__half2*)d_W;
        #pragma unroll
        for (int rt = 0; rt < 8; rt++) {
            const int r0 = rt * 16;
            float acc[4][4];
            #pragma unroll
            for (int nt = 0; nt < 4; nt++)
                acc[nt][0] = acc[nt][1] = acc[nt][2] = acc[nt][3] = 0.f;
            #pragma unroll
            for (int ks = 0; ks < 8; ks++) {
                uint32_t a[4];
                ldsm_x4(a, sA2 + ((r0 + lrow) * ST + ks * 16 + lcol) * 2);
                #pragma unroll
                for (int nt = 0; nt < 4; nt++)
                    mma16816(acc[nt], a[0], a[1], a[2], a[3],
                             B3[nt][ks][0], B3[nt][ks][1]);
            }
            #pragma unroll
            for (int nt = 0; nt < 4; nt++) {
                int col = c0 + nt * 8 + tg * 2;
                __half2 h0 = __floats2half2_rn(acc[nt][0] + biasA[nt], acc[nt][1] + biasB[nt]);
                __half2 h1 = __floats2half2_rn(acc[nt][2] + biasA[nt], acc[nt][3] + biasB[nt]);
                stcs_u32(&Wg[(ebase + r0 + g) * 128 + (col >> 1)], *(uint32_t*)&h0);
                stcs_u32(&Wg[(ebase + r0 + g + 8) * 128 + (col >> 1)], *(uint32_t*)&h1);
            }
        }
    }
}

// msg = h[src] @ W_e ; vector scatter-add into agg[dst]
__global__ void k_conv(const void* __restrict__ ei, const float* __restrict__ hin)
{
    long long e = (long long)blockIdx.x * 32 + (threadIdx.x >> 3);
    int o = threadIdx.x & 7;           // output half2 index (cols 2o, 2o+1)
    if (e >= EE) return;
    long long src, dst;
    if (d_is64) {
        const long long* p = (const long long*)ei;
        src = p[e]; dst = p[EE + e];
    } else {
        const int* p = (const int*)ei;
        src = p[e]; dst = p[EE + e];
    }
    const float4* hr4 = (const float4*)(hin + src * EMB);
    float4 h0 = hr4[0], h1 = hr4[1], h2 = hr4[2], h3 = hr4[3];
    float hr[16] = {h0.x,h0.y,h0.z,h0.w, h1.x,h1.y,h1.z,h1.w,
                    h2.x,h2.y,h2.z,h2.w, h3.x,h3.y,h3.z,h3.w};
    const __half2* Wr = (const __half2*)(d_W + e * 256);
    float mx = 0.f, my = 0.f;
    #pragma unroll
    for (int i = 0; i < 16; i++) {
        float2 wf = __half22float2(__ldcs(&Wr[i * 8 + o]));
        mx = fmaf(hr[i], wf.x, mx);
        my = fmaf(hr[i], wf.y, my);
    }
    float* dp = &d_agg[dst * EMB + 2 * o];
    asm volatile("red.global.add.v2.f32 [%0], {%1,%2};\n"
                 :: "l"(dp), "f"(mx), "f"(my) : "memory");
}

// h_out = relu(agg/denom + h_in @ root_w + conv_b); zero agg for next round
__global__ void k_update(const float* __restrict__ hin, float* __restrict__ hout,
                         const float* __restrict__ root_w, const float* __restrict__ conv_b)
{
    int t = blockIdx.x * blockDim.x + threadIdx.x;
    if (t >= NN * EMB) return;
    int n = t >> 4, o = t & 15;
    float denom = fmaxf(d_cnt[n], 1.f);
    float v = d_agg[t] / denom;
    const float* hr = hin + n * EMB;
    #pragma unroll
    for (int i = 0; i < 16; i++) v = fmaf(hr[i], root_w[i * EMB + o], v);
    v += conv_b[o];
    hout[t] = fmaxf(v, 0.f);
    d_agg[t] = 0.f;
}

__global__ void k_out(const float* __restrict__ hin,
                      const float* __restrict__ inv_w, const float* __restrict__ inv_b,
                      float* __restrict__ out)
{
    int t = blockIdx.x * blockDim.x + threadIdx.x;
    if (t >= NN * 3) return;
    int n = t / 3, f = t % 3;
    float v = inv_b[f];
    const float* hr = hin + n * EMB;
    #pragma unroll
    for (int i = 0; i < 16; i++) v = fmaf(hr[i], inv_w[i * 3 + f], v);
    out[t] = v;
}

// ---------------- launcher ----------------
extern "C" void kernel_launch(void* const* d_in, const int* in_sizes, int n_in,
                              void* d_out, int out_size)
{
    const float* x      = (const float*)d_in[0];
    const void*  ei     = d_in[1];
    const float* ea     = (const float*)d_in[2];
    const float* emb_w  = (const float*)d_in[3];
    const float* emb_b  = (const float*)d_in[4];
    const float* k1_w   = (const float*)d_in[5];
    const float* k1_b   = (const float*)d_in[6];
    const float* k2_w   = (const float*)d_in[7];
    const float* k2_b   = (const float*)d_in[8];
    const float* k3_w   = (const float*)d_in[9];
    const float* k3_b   = (const float*)d_in[10];
    const float* root_w = (const float*)d_in[11];
    const float* conv_b = (const float*)d_in[12];
    const float* inv_w  = (const float*)d_in[13];
    const float* inv_b  = (const float*)d_in[14];
    float* out = (float*)d_out;

    const int ST = KW + 8;
    const int smemBytes = (2 * 128 * ST + 128 * 8) * (int)sizeof(__half);  // 71680
    cudaFuncSetAttribute(k_mlp, cudaFuncAttributeMaxDynamicSharedMemorySize, smemBytes);

    static float* hA = nullptr;
    static float* hB = nullptr;
    if (!hA) {
        cudaGetSymbolAddress((void**)&hA, d_hA);
        cudaGetSymbolAddress((void**)&hB, d_hB);
    }

    // k_mlp kept in the ncu-profiled launch slot.
    k_detect<<<1, 256>>>((const int*)ei);
    k_prep<<<(KW * KW + 256 * KW + 255) / 256, 256>>>(k2_w, k3_w);
    k_init<<<(NN * EMB + 255) / 256, 256>>>(x, emb_w, emb_b);
    k_mlp<<<EE / 128, 256, smemBytes>>>(ea, k1_w, k1_b, k2_b, k3_b);
    k_cnt<<<(EE + 255) / 256, 256>>>(ei);

    float* hin  = hA;
    float* hout = hB;
    for (int it = 0; it < NCONV; it++) {
        k_conv<<<EE / 32, 256>>>(ei, hin);
        k_update<<<(NN * EMB + 255) / 256, 256>>>(hin, hout, root_w, conv_b);
        float* tmp = hin; hin = hout; hout = tmp;
    }
    k_out<<<(NN * 3 + 255) / 256, 256>>>(hin, inv_w, inv_b, out);
}

// round 7
// speedup vs baseline: 3.5281x; 1.3212x over previous
#include <cuda_runtime.h>
#include <cuda_fp16.h>
#include <cstdint>

#define NN   50000
#define EE   800000
#define EMB  16
#define KW   128
#define NCONV 4

// ---------------- device scratch (no cudaMalloc allowed) ----------------
__device__ __half  d_W[(size_t)EE * 256];     // per-edge 16x16 W, fragment-permuted fp16
__device__ float   d_hA[NN * EMB];
__device__ float   d_hB[NN * EMB];
__device__ float   d_agg[NN * EMB];
__device__ float   d_cnt[NN];
__device__ __half2 d_k2p[8192];               // k2 fragments: [w][chunk8][lane][4]
__device__ __half2 d_k3p[16384];              // k3 fragments: [w][chunk16][lane][4]
__device__ int     d_is64;

// ---------------- helpers ----------------
__device__ __forceinline__ void mma16816(float* c,
    uint32_t a0, uint32_t a1, uint32_t a2, uint32_t a3,
    uint32_t b0, uint32_t b1)
{
    asm volatile(
        "mma.sync.aligned.m16n8k16.row.col.f32.f16.f16.f32 "
        "{%0,%1,%2,%3},{%4,%5,%6,%7},{%8,%9},{%0,%1,%2,%3};\n"
        : "+f"(c[0]), "+f"(c[1]), "+f"(c[2]), "+f"(c[3])
        : "r"(a0), "r"(a1), "r"(a2), "r"(a3), "r"(b0), "r"(b1));
}

__device__ __forceinline__ void mma16808(float* c, uint32_t a0, uint32_t a1, uint32_t b0)
{
    asm volatile(
        "mma.sync.aligned.m16n8k8.row.col.f32.f16.f16.f32 "
        "{%0,%1,%2,%3},{%4,%5},{%6},{%0,%1,%2,%3};\n"
        : "+f"(c[0]), "+f"(c[1]), "+f"(c[2]), "+f"(c[3])
        : "r"(a0), "r"(a1), "r"(b0));
}

__device__ __forceinline__ void ldsm_x4(uint32_t* a, uint32_t saddr)
{
    asm volatile(
        "ldmatrix.sync.aligned.m8n8.x4.shared.b16 {%0,%1,%2,%3}, [%4];\n"
        : "=r"(a[0]), "=r"(a[1]), "=r"(a[2]), "=r"(a[3]) : "r"(saddr));
}

__device__ __forceinline__ void ldsm_x2(uint32_t* a, uint32_t saddr)
{
    asm volatile(
        "ldmatrix.sync.aligned.m8n8.x2.shared.b16 {%0,%1}, [%2];\n"
        : "=r"(a[0]), "=r"(a[1]) : "r"(saddr));
}

__device__ __forceinline__ void stcs_v4(void* p, uint32_t x, uint32_t y, uint32_t z, uint32_t w)
{
    asm volatile("st.global.cs.v4.b32 [%0], {%1,%2,%3,%4};\n"
                 :: "l"(p), "r"(x), "r"(y), "r"(z), "r"(w) : "memory");
}

// ---------------- kernels ----------------

__global__ void k_detect(const int* __restrict__ ei)
{
    __shared__ int anynz;
    if (threadIdx.x == 0) anynz = 0;
    __syncthreads();
    int v = ei[2 * threadIdx.x + 1];
    if (v != 0) atomicOr(&anynz, 1);
    __syncthreads();
    if (threadIdx.x == 0) d_is64 = (anynz == 0) ? 1 : 0;
}

// Build fragment-permuted fp16 tables for layers 2 and 3.
// Per-thread fragment q=(nt*16+ks*2+h): half2 = (kw[k][n], kw[k+1][n]),
// k = ks*16+h*8+tg*2, n = w*COLS + nt*8 + g.
__global__ void k_prep(const float* __restrict__ k2w, const float* __restrict__ k3w)
{
    int t = blockIdx.x * blockDim.x + threadIdx.x;
    if (t < 8192) {            // stage-2 table: 8 warps x 8 chunks x 32 lanes x 4
        int j = t & 3, l = (t >> 2) & 31, c = (t >> 7) & 7, w = t >> 10;
        int q = c * 4 + j;
        int nt = q >> 4, ks = (q >> 1) & 7, h = q & 1;
        int g = l >> 2, tg = l & 3;
        int n = w * 16 + nt * 8 + g;
        int k = ks * 16 + h * 8 + tg * 2;
        d_k2p[t] = __floats2half2_rn(k2w[k * KW + n], k2w[(k + 1) * KW + n]);
    } else if (t < 8192 + 16384) {  // stage-3 table: 8 x 16 x 32 x 4
        int t2 = t - 8192;
        int j = t2 & 3, l = (t2 >> 2) & 31, c = (t2 >> 7) & 15, w = t2 >> 11;
        int q = c * 4 + j;
        int nt = q >> 4, ks = (q >> 1) & 7, h = q & 1;
        int g = l >> 2, tg = l & 3;
        int n = w * 32 + nt * 8 + g;
        int k = ks * 16 + h * 8 + tg * 2;
        d_k3p[t2] = __floats2half2_rn(k3w[k * 256 + n], k3w[(k + 1) * 256 + n]);
    }
}

__global__ void k_init(const float* __restrict__ x,
                       const float* __restrict__ emb_w,
                       const float* __restrict__ emb_b)
{
    int t = blockIdx.x * blockDim.x + threadIdx.x;
    if (t >= NN * EMB) return;
    int n = t >> 4, o = t & 15;
    float v = emb_b[o];
    #pragma unroll
    for (int f = 0; f < 3; f++) v += x[n * 3 + f] * emb_w[f * EMB + o];
    d_hA[t]  = v;
    d_agg[t] = 0.f;
    if (o == 0) d_cnt[n] = 0.f;
}

__global__ void k_cnt(const void* __restrict__ ei)
{
    long long e = (long long)blockIdx.x * blockDim.x + threadIdx.x;
    if (e >= EE) return;
    long long dst;
    if (d_is64) dst = ((const long long*)ei)[EE + e];
    else        dst = ((const int*)ei)[EE + e];
    atomicAdd(&d_cnt[dst], 1.f);
}

// Fused edge-MLP: 128 edges/block, all layers on tensor cores.
// B fragments via vectorized pre-permuted tables; W stored fragment-permuted
// with 128-bit streaming stores.
__global__ __launch_bounds__(256, 2) void k_mlp(
    const float* __restrict__ ea,
    const float* __restrict__ k1w, const float* __restrict__ k1b,
    const float* __restrict__ k2b, const float* __restrict__ k3b)
{
    const int ST = KW + 8;                 // smem row stride in halves
    extern __shared__ __half sm[];
    __half* A1 = sm;                       // e1: 128 x ST
    __half* A2 = A1 + 128 * ST;            // e2: 128 x ST
    __half* EA = A2 + 128 * ST;            // ea fp16: 128 x 8

    const int tid  = threadIdx.x;
    const int warp = tid >> 5;
    const int lane = tid & 31;
    const int g    = lane >> 2;
    const int tg   = lane & 3;
    const long long ebase = (long long)blockIdx.x * 128;

    const uint32_t sA1 = (uint32_t)__cvta_generic_to_shared(A1);
    const uint32_t sA2 = (uint32_t)__cvta_generic_to_shared(A2);
    const uint32_t sEA = (uint32_t)__cvta_generic_to_shared(EA);
    const uint32_t lrow = (lane & 15);
    const uint32_t lcol = (lane >> 4) * 8;

    // ---- stage 0: ea -> fp16 smem tile [128 x 8] ----
    if (tid < 128) {
        const float* er = ea + (ebase + tid) * 6;
        float a0 = er[0], a1 = er[1], a2 = er[2], a3 = er[3], a4 = er[4], a5 = er[5];
        __half2* row = (__half2*)(EA + tid * 8);
        row[0] = __floats2half2_rn(a0, a1);
        row[1] = __floats2half2_rn(a2, a3);
        row[2] = __floats2half2_rn(a4, a5);
        row[3] = __floats2half2_rn(0.f, 0.f);
    }

    // ---- stage 1: e1 = relu(ea @ k1_w + k1_b) via m16n8k8 ----
    {
        const int c0 = warp * 16;
        uint32_t B1[2];
        #pragma unroll
        for (int nt = 0; nt < 2; nt++) {
            int n  = c0 + nt * 8 + g;
            int k0 = tg * 2;
            float f0 = (k0     < 6) ? k1w[k0 * KW + n]       : 0.f;
            float f1 = (k0 + 1 < 6) ? k1w[(k0 + 1) * KW + n] : 0.f;
            __half2 hv = __floats2half2_rn(f0, f1);
            B1[nt] = *(uint32_t*)&hv;
        }
        float bias0 = k1b[c0 + tg * 2],     bias1 = k1b[c0 + tg * 2 + 1];
        float bias2 = k1b[c0 + 8 + tg * 2], bias3 = k1b[c0 + 8 + tg * 2 + 1];
        __syncthreads();   // EA tile ready

        #pragma unroll
        for (int rt = 0; rt < 8; rt++) {
            uint32_t a[2];
            ldsm_x2(a, sEA + (uint32_t)(rt * 16 + lrow) * 16);
            float acc0[4] = {0.f, 0.f, 0.f, 0.f};
            float acc1[4] = {0.f, 0.f, 0.f, 0.f};
            mma16808(acc0, a[0], a[1], B1[0]);
            mma16808(acc1, a[0], a[1], B1[1]);
            int r0 = rt * 16;
            *(__half2*)&A1[(r0 + g) * ST + c0 + tg * 2] = __floats2half2_rn(
                fmaxf(acc0[0] + bias0, 0.f), fmaxf(acc0[1] + bias1, 0.f));
            *(__half2*)&A1[(r0 + g + 8) * ST + c0 + tg * 2] = __floats2half2_rn(
                fmaxf(acc0[2] + bias0, 0.f), fmaxf(acc0[3] + bias1, 0.f));
            *(__half2*)&A1[(r0 + g) * ST + c0 + 8 + tg * 2] = __floats2half2_rn(
                fmaxf(acc1[0] + bias2, 0.f), fmaxf(acc1[1] + bias3, 0.f));
            *(__half2*)&A1[(r0 + g + 8) * ST + c0 + 8 + tg * 2] = __floats2half2_rn(
                fmaxf(acc1[2] + bias2, 0.f), fmaxf(acc1[3] + bias3, 0.f));
        }
    }
    __syncthreads();

    // ---- stage 2: e2 = relu(e1 @ k2_w + k2_b) ----
    {
        const int c0 = warp * 16;
        uint32_t B2f[32];                  // [nt*16 + ks*2 + h]
        {
            const uint4* tp = ((const uint4*)d_k2p) + (warp * 8) * 32 + lane;
            #pragma unroll
            for (int c = 0; c < 8; c++) {
                uint4 v = tp[c * 32];
                B2f[c * 4 + 0] = v.x; B2f[c * 4 + 1] = v.y;
                B2f[c * 4 + 2] = v.z; B2f[c * 4 + 3] = v.w;
            }
        }
        float bias0 = k2b[c0 + tg * 2],     bias1 = k2b[c0 + tg * 2 + 1];
        float bias2 = k2b[c0 + 8 + tg * 2], bias3 = k2b[c0 + 8 + tg * 2 + 1];

        #pragma unroll
        for (int rt = 0; rt < 8; rt++) {
            const int r0 = rt * 16;
            float acc[2][4];
            #pragma unroll
            for (int nt = 0; nt < 2; nt++)
                acc[nt][0] = acc[nt][1] = acc[nt][2] = acc[nt][3] = 0.f;
            #pragma unroll
            for (int ks = 0; ks < 8; ks++) {
                uint32_t a[4];
                ldsm_x4(a, sA1 + ((r0 + lrow) * ST + ks * 16 + lcol) * 2);
                mma16816(acc[0], a[0], a[1], a[2], a[3], B2f[ks * 2], B2f[ks * 2 + 1]);
                mma16816(acc[1], a[0], a[1], a[2], a[3], B2f[16 + ks * 2], B2f[16 + ks * 2 + 1]);
            }
            #pragma unroll
            for (int nt = 0; nt < 2; nt++) {
                float ba = (nt == 0) ? bias0 : bias2;
                float bb = (nt == 0) ? bias1 : bias3;
                int col = c0 + nt * 8 + tg * 2;
                *(__half2*)&A2[(r0 + g) * ST + col] = __floats2half2_rn(
                    fmaxf(acc[nt][0] + ba, 0.f), fmaxf(acc[nt][1] + bb, 0.f));
                *(__half2*)&A2[(r0 + g + 8) * ST + col] = __floats2half2_rn(
                    fmaxf(acc[nt][2] + ba, 0.f), fmaxf(acc[nt][3] + bb, 0.f));
            }
        }
    }
    __syncthreads();

    // ---- stage 3: W = e2 @ k3_w + k3_b -> permuted fp16 global (128-bit cs) ----
    {
        const int c0 = warp * 32;
        uint32_t B3f[64];                  // [nt*16 + ks*2 + h]
        {
            const uint4* tp = ((const uint4*)d_k3p) + (warp * 16) * 32 + lane;
            #pragma unroll
            for (int c = 0; c < 16; c++) {
                uint4 v = tp[c * 32];
                B3f[c * 4 + 0] = v.x; B3f[c * 4 + 1] = v.y;
                B3f[c * 4 + 2] = v.z; B3f[c * 4 + 3] = v.w;
            }
        }
        float biasA[4], biasB[4];
        #pragma unroll
        for (int nt = 0; nt < 4; nt++) {
            biasA[nt] = k3b[c0 + nt * 8 + tg * 2];
            biasB[nt] = k3b[c0 + nt * 8 + tg * 2 + 1];
        }

        #pragma unroll
        for (int rt = 0; rt < 8; rt++) {
            const int r0 = rt * 16;
            float acc[4][4];
            #pragma unroll
            for (int nt = 0; nt < 4; nt++)
                acc[nt][0] = acc[nt][1] = acc[nt][2] = acc[nt][3] = 0.f;
            #pragma unroll
            for (int ks = 0; ks < 8; ks++) {
                uint32_t a[4];
                ldsm_x4(a, sA2 + ((r0 + lrow) * ST + ks * 16 + lcol) * 2);
                #pragma unroll
                for (int nt = 0; nt < 4; nt++)
                    mma16816(acc[nt], a[0], a[1], a[2], a[3],
                             B3f[nt * 16 + ks * 2], B3f[nt * 16 + ks * 2 + 1]);
            }
            // permuted W store: pos (c0 + tg*8 + nt*2 + b) holds logical col
            // (c0 + nt*8 + tg*2 + b). Per row-half one uint4.
            uint32_t p0[4], p1[4];
            #pragma unroll
            for (int nt = 0; nt < 4; nt++) {
                __half2 h0 = __floats2half2_rn(acc[nt][0] + biasA[nt], acc[nt][1] + biasB[nt]);
                __half2 h1 = __floats2half2_rn(acc[nt][2] + biasA[nt], acc[nt][3] + biasB[nt]);
                p0[nt] = *(uint32_t*)&h0;
                p1[nt] = *(uint32_t*)&h1;
            }
            __half* base0 = d_W + (ebase + r0 + g) * 256 + c0 + tg * 8;
            __half* base1 = d_W + (ebase + r0 + g + 8) * 256 + c0 + tg * 8;
            stcs_v4(base0, p0[0], p0[1], p0[2], p0[3]);
            stcs_v4(base1, p1[0], p1[1], p1[2], p1[3]);
        }
    }
}

// msg = h[src] @ W_e (permuted layout) ; vector scatter-add into agg[dst]
__global__ void k_conv(const void* __restrict__ ei, const float* __restrict__ hin)
{
    long long e = (long long)blockIdx.x * 32 + (threadIdx.x >> 3);
    int o = threadIdx.x & 7;           // output half2 index (cols 2o, 2o+1)
    if (e >= EE) return;
    long long src, dst;
    if (d_is64) {
        const long long* p = (const long long*)ei;
        src = p[e]; dst = p[EE + e];
    } else {
        const int* p = (const int*)ei;
        src = p[e]; dst = p[EE + e];
    }
    const float4* hr4 = (const float4*)(hin + src * EMB);
    float4 h0 = hr4[0], h1 = hr4[1], h2 = hr4[2], h3 = hr4[3];
    float hr[16] = {h0.x,h0.y,h0.z,h0.w, h1.x,h1.y,h1.z,h1.w,
                    h2.x,h2.y,h2.z,h2.w, h3.x,h3.y,h3.z,h3.w};
    const __half2* Wr = (const __half2*)(d_W + e * 256);
    const int oa = (o & 3) * 4 + (o >> 2);   // permutation constant for this o
    float mx = 0.f, my = 0.f;
    #pragma unroll
    for (int i = 0; i < 16; i++) {
        // inverse fragment permutation: logical col i*16+2o(+1)
        int idx = (i >> 1) * 16 + (i & 1) * 2 + oa;
        float2 wf = __half22float2(__ldcs(&Wr[idx]));
        mx = fmaf(hr[i], wf.x, mx);
        my = fmaf(hr[i], wf.y, my);
    }
    float* dp = &d_agg[dst * EMB + 2 * o];
    asm volatile("red.global.add.v2.f32 [%0], {%1,%2};\n"
                 :: "l"(dp), "f"(mx), "f"(my) : "memory");
}

// h_out = relu(agg/denom + h_in @ root_w + conv_b); zero agg for next round
__global__ void k_update(const float* __restrict__ hin, float* __restrict__ hout,
                         const float* __restrict__ root_w, const float* __restrict__ conv_b)
{
    int t = blockIdx.x * blockDim.x + threadIdx.x;
    if (t >= NN * EMB) return;
    int n = t >> 4, o = t & 15;
    float denom = fmaxf(d_cnt[n], 1.f);
    float v = d_agg[t] / denom;
    const float* hr = hin + n * EMB;
    #pragma unroll
    for (int i = 0; i < 16; i++) v = fmaf(hr[i], root_w[i * EMB + o], v);
    v += conv_b[o];
    hout[t] = fmaxf(v, 0.f);
    d_agg[t] = 0.f;
}

__global__ void k_out(const float* __restrict__ hin,
                      const float* __restrict__ inv_w, const float* __restrict__ inv_b,
                      float* __restrict__ out)
{
    int t = blockIdx.x * blockDim.x + threadIdx.x;
    if (t >= NN * 3) return;
    int n = t / 3, f = t % 3;
    float v = inv_b[f];
    const float* hr = hin + n * EMB;
    #pragma unroll
    for (int i = 0; i < 16; i++) v = fmaf(hr[i], inv_w[i * 3 + f], v);
    out[t] = v;
}

// ---------------- launcher ----------------
extern "C" void kernel_launch(void* const* d_in, const int* in_sizes, int n_in,
                              void* d_out, int out_size)
{
    const float* x      = (const float*)d_in[0];
    const void*  ei     = d_in[1];
    const float* ea     = (const float*)d_in[2];
    const float* emb_w  = (const float*)d_in[3];
    const float* emb_b  = (const float*)d_in[4];
    const float* k1_w   = (const float*)d_in[5];
    const float* k1_b   = (const float*)d_in[6];
    const float* k2_w   = (const float*)d_in[7];
    const float* k2_b   = (const float*)d_in[8];
    const float* k3_w   = (const float*)d_in[9];
    const float* k3_b   = (const float*)d_in[10];
    const float* root_w = (const float*)d_in[11];
    const float* conv_b = (const float*)d_in[12];
    const float* inv_w  = (const float*)d_in[13];
    const float* inv_b  = (const float*)d_in[14];
    float* out = (float*)d_out;

    const int ST = KW + 8;
    const int smemBytes = (2 * 128 * ST + 128 * 8) * (int)sizeof(__half);  // 71680
    cudaFuncSetAttribute(k_mlp, cudaFuncAttributeMaxDynamicSharedMemorySize, smemBytes);

    static float* hA = nullptr;
    static float* hB = nullptr;
    if (!hA) {
        cudaGetSymbolAddress((void**)&hA, d_hA);
        cudaGetSymbolAddress((void**)&hB, d_hB);
    }

    // k_mlp kept in the ncu-profiled launch slot.
    k_detect<<<1, 256>>>((const int*)ei);
    k_prep<<<(8192 + 16384 + 255) / 256, 256>>>(k2_w, k3_w);
    k_init<<<(NN * EMB + 255) / 256, 256>>>(x, emb_w, emb_b);
    k_mlp<<<EE / 128, 256, smemBytes>>>(ea, k1_w, k1_b, k2_b, k3_b);
    k_cnt<<<(EE + 255) / 256, 256>>>(ei);

    float* hin  = hA;
    float* hout = hB;
    for (int it = 0; it < NCONV; it++) {
        k_conv<<<EE / 32, 256>>>(ei, hin);
        k_update<<<(NN * EMB + 255) / 256, 256>>>(hin, hout, root_w, conv_b);
        float* tmp = hin; hin = hout; hout = tmp;
    }
    k_out<<<(NN * 3 + 255) / 256, 256>>>(hin, inv_w, inv_b, out);
}

// round 9
// speedup vs baseline: 3.5404x; 1.0035x over previous
#include <cuda_runtime.h>
#include <cuda_fp16.h>
#include <cstdint>

#define NN   50000
#define EE   800000
#define EMB  16
#define KW   128
#define NCONV 4

// ---------------- device scratch (no cudaMalloc allowed) ----------------
__device__ __half  d_W[(size_t)EE * 256];     // per-edge 16x16 W, fragment-permuted fp16
__device__ float   d_hA[NN * EMB];
__device__ float   d_hB[NN * EMB];
__device__ float   d_agg[NN * EMB];
__device__ float   d_cnt[NN];
__device__ __half2 d_k2p[8192];               // k2 fragments: [colQ][chunk16][lane][4]
__device__ __half2 d_k3p[16384];              // k3 fragments: [warp][chunk16][lane][4]
__device__ int     d_is64;

// ---------------- helpers ----------------
__device__ __forceinline__ void mma16816(float* c,
    uint32_t a0, uint32_t a1, uint32_t a2, uint32_t a3,
    uint32_t b0, uint32_t b1)
{
    asm volatile(
        "mma.sync.aligned.m16n8k16.row.col.f32.f16.f16.f32 "
        "{%0,%1,%2,%3},{%4,%5,%6,%7},{%8,%9},{%0,%1,%2,%3};\n"
        : "+f"(c[0]), "+f"(c[1]), "+f"(c[2]), "+f"(c[3])
        : "r"(a0), "r"(a1), "r"(a2), "r"(a3), "r"(b0), "r"(b1));
}

__device__ __forceinline__ void mma16808(float* c, uint32_t a0, uint32_t a1, uint32_t b0)
{
    asm volatile(
        "mma.sync.aligned.m16n8k8.row.col.f32.f16.f16.f32 "
        "{%0,%1,%2,%3},{%4,%5},{%6},{%0,%1,%2,%3};\n"
        : "+f"(c[0]), "+f"(c[1]), "+f"(c[2]), "+f"(c[3])
        : "r"(a0), "r"(a1), "r"(b0));
}

__device__ __forceinline__ void ldsm_x4(uint32_t* a, uint32_t saddr)
{
    asm volatile(
        "ldmatrix.sync.aligned.m8n8.x4.shared.b16 {%0,%1,%2,%3}, [%4];\n"
        : "=r"(a[0]), "=r"(a[1]), "=r"(a[2]), "=r"(a[3]) : "r"(saddr));
}

__device__ __forceinline__ void ldsm_x2(uint32_t* a, uint32_t saddr)
{
    asm volatile(
        "ldmatrix.sync.aligned.m8n8.x2.shared.b16 {%0,%1}, [%2];\n"
        : "=r"(a[0]), "=r"(a[1]) : "r"(saddr));
}

__device__ __forceinline__ void stcs_v4(void* p, uint32_t x, uint32_t y, uint32_t z, uint32_t w)
{
    asm volatile("st.global.cs.v4.b32 [%0], {%1,%2,%3,%4};\n"
                 :: "l"(p), "r"(x), "r"(y), "r"(z), "r"(w) : "memory");
}

// ---------------- kernels ----------------

__global__ void k_detect(const int* __restrict__ ei)
{
    __shared__ int anynz;
    if (threadIdx.x == 0) anynz = 0;
    __syncthreads();
    int v = ei[2 * threadIdx.x + 1];
    if (v != 0) atomicOr(&anynz, 1);
    __syncthreads();
    if (threadIdx.x == 0) d_is64 = (anynz == 0) ? 1 : 0;
}

// Build fragment-permuted fp16 B tables for layers 2 and 3.
// K indices incorporate the permuted A1/A2 smem layouts (see k_mlp epilogues):
//   stage2: k = ks*16 + (tg&1)*8 + (h*2 + (tg>>1))*2    (A1 perm: pos=tg*4+j)
//   stage3: k = (ks>>1)*32 + tg*8 + ((ks&1)*2 + h)*2    (A2 perm: pos=tg*8+nt*2+b)
__global__ void k_prep(const float* __restrict__ k2w, const float* __restrict__ k3w)
{
    int t = blockIdx.x * blockDim.x + threadIdx.x;
    if (t < 8192) {            // stage-2 table: 4 colQ x 16 chunks x 32 lanes x 4
        int j = t & 3, l = (t >> 2) & 31, c = (t >> 7) & 15, cq = t >> 11;  // FIXED: >>11
        int q = c * 4 + j;                       // nt*16 + ks*2 + h
        int nt = q >> 4, ks = (q >> 1) & 7, h = q & 1;
        int g = l >> 2, tg = l & 3;
        int n = cq * 32 + nt * 8 + g;
        int k = ks * 16 + (tg & 1) * 8 + (h * 2 + (tg >> 1)) * 2;
        d_k2p[t] = __floats2half2_rn(k2w[k * KW + n], k2w[(k + 1) * KW + n]);
    } else if (t < 8192 + 16384) {  // stage-3 table: 8 warps x 16 chunks x 32 lanes x 4
        int t2 = t - 8192;
        int j = t2 & 3, l = (t2 >> 2) & 31, c = (t2 >> 7) & 15, w = t2 >> 11;
        int q = c * 4 + j;
        int nt = q >> 4, ks = (q >> 1) & 7, h = q & 1;
        int g = l >> 2, tg = l & 3;
        int n = w * 32 + nt * 8 + g;
        int k = (ks >> 1) * 32 + tg * 8 + ((ks & 1) * 2 + h) * 2;
        d_k3p[t2] = __floats2half2_rn(k3w[k * 256 + n], k3w[(k + 1) * 256 + n]);
    }
}

__global__ void k_init(const float* __restrict__ x,
                       const float* __restrict__ emb_w,
                       const float* __restrict__ emb_b)
{
    int t = blockIdx.x * blockDim.x + threadIdx.x;
    if (t >= NN * EMB) return;
    int n = t >> 4, o = t & 15;
    float v = emb_b[o];
    #pragma unroll
    for (int f = 0; f < 3; f++) v += x[n * 3 + f] * emb_w[f * EMB + o];
    d_hA[t]  = v;
    d_agg[t] = 0.f;
    if (o == 0) d_cnt[n] = 0.f;
}

__global__ void k_cnt(const void* __restrict__ ei)
{
    long long e = (long long)blockIdx.x * blockDim.x + threadIdx.x;
    if (e >= EE) return;
    long long dst;
    if (d_is64) dst = ((const long long*)ei)[EE + e];
    else        dst = ((const int*)ei)[EE + e];
    atomicAdd(&d_cnt[dst], 1.f);
}

// Fused edge-MLP: 128 edges/block, all layers on tensor cores.
// Stage2 uses 2D warp tiling (row-half x col-quarter) to halve LDSM traffic;
// A1/A2 use K-permuted layouts so epilogue stores are 64/128-bit.
__global__ __launch_bounds__(256, 2) void k_mlp(
    const float* __restrict__ ea,
    const float* __restrict__ k1w, const float* __restrict__ k1b,
    const float* __restrict__ k2b, const float* __restrict__ k3b)
{
    const int ST = KW + 8;                 // smem row stride in halves (272B, 16B-mult)
    extern __shared__ __half sm[];
    __half* A1 = sm;                       // e1: 128 x ST (K-permuted per 16-block)
    __half* A2 = A1 + 128 * ST;            // e2: 128 x ST (K-permuted per 32-block)
    __half* EA = A2 + 128 * ST;            // ea fp16: 128 x 8

    const int tid  = threadIdx.x;
    const int warp = tid >> 5;
    const int lane = tid & 31;
    const int g    = lane >> 2;
    const int tg   = lane & 3;
    const long long ebase = (long long)blockIdx.x * 128;

    const uint32_t sA1 = (uint32_t)__cvta_generic_to_shared(A1);
    const uint32_t sA2 = (uint32_t)__cvta_generic_to_shared(A2);
    const uint32_t sEA = (uint32_t)__cvta_generic_to_shared(EA);
    const uint32_t lrow = (lane & 15);
    const uint32_t lcol = (lane >> 4) * 8;

    // ---- stage 0: ea -> fp16 smem tile [128 x 8] ----
    if (tid < 128) {
        const float* er = ea + (ebase + tid) * 6;
        float a0 = er[0], a1 = er[1], a2 = er[2], a3 = er[3], a4 = er[4], a5 = er[5];
        __half2* row = (__half2*)(EA + tid * 8);
        row[0] = __floats2half2_rn(a0, a1);
        row[1] = __floats2half2_rn(a2, a3);
        row[2] = __floats2half2_rn(a4, a5);
        row[3] = __floats2half2_rn(0.f, 0.f);
    }

    // ---- stage 1: e1 = relu(ea @ k1_w + k1_b) via m16n8k8 -> permuted A1 ----
    {
        const int c0 = warp * 16;
        uint32_t B1[2];
        #pragma unroll
        for (int nt = 0; nt < 2; nt++) {
            int n  = c0 + nt * 8 + g;
            int k0 = tg * 2;
            float f0 = (k0     < 6) ? k1w[k0 * KW + n]       : 0.f;
            float f1 = (k0 + 1 < 6) ? k1w[(k0 + 1) * KW + n] : 0.f;
            __half2 hv = __floats2half2_rn(f0, f1);
            B1[nt] = *(uint32_t*)&hv;
        }
        float bias0 = k1b[c0 + tg * 2],     bias1 = k1b[c0 + tg * 2 + 1];
        float bias2 = k1b[c0 + 8 + tg * 2], bias3 = k1b[c0 + 8 + tg * 2 + 1];
        __syncthreads();   // EA tile ready

        #pragma unroll
        for (int rt = 0; rt < 8; rt++) {
            uint32_t a[2];
            ldsm_x2(a, sEA + (uint32_t)(rt * 16 + lrow) * 16);
            float acc0[4] = {0.f, 0.f, 0.f, 0.f};
            float acc1[4] = {0.f, 0.f, 0.f, 0.f};
            mma16808(acc0, a[0], a[1], B1[0]);
            mma16808(acc1, a[0], a[1], B1[1]);
            int r0 = rt * 16;
            // permuted store: pos c0 + tg*4 + {0,1,2,3} <- cols {tg*2,tg*2+1,8+tg*2,8+tg*2+1}
            __half2 q0 = __floats2half2_rn(
                fmaxf(acc0[0] + bias0, 0.f), fmaxf(acc0[1] + bias1, 0.f));
            __half2 q1 = __floats2half2_rn(
                fmaxf(acc1[0] + bias2, 0.f), fmaxf(acc1[1] + bias3, 0.f));
            *(uint2*)&A1[(r0 + g) * ST + c0 + tg * 4] =
                make_uint2(*(uint32_t*)&q0, *(uint32_t*)&q1);
            __half2 q2 = __floats2half2_rn(
                fmaxf(acc0[2] + bias0, 0.f), fmaxf(acc0[3] + bias1, 0.f));
            __half2 q3 = __floats2half2_rn(
                fmaxf(acc1[2] + bias2, 0.f), fmaxf(acc1[3] + bias3, 0.f));
            *(uint2*)&A1[(r0 + g + 8) * ST + c0 + tg * 4] =
                make_uint2(*(uint32_t*)&q2, *(uint32_t*)&q3);
        }
    }
    __syncthreads();

    // ---- stage 2: e2 = relu(e1 @ k2_w + k2_b), 2D warp tiling ----
    {
        const int colQ = warp & 3;         // 32-col quarter
        const int rowH = warp >> 2;        // 64-row half
        const int c0 = colQ * 32;
        uint32_t B2f[64];                  // [nt*16 + ks*2 + h]
        {
            const uint4* tp = ((const uint4*)d_k2p) + (colQ * 16) * 32 + lane;
            #pragma unroll
            for (int c = 0; c < 16; c++) {
                uint4 v = tp[c * 32];
                B2f[c * 4 + 0] = v.x; B2f[c * 4 + 1] = v.y;
                B2f[c * 4 + 2] = v.z; B2f[c * 4 + 3] = v.w;
            }
        }
        float biasA[4], biasB[4];
        #pragma unroll
        for (int nt = 0; nt < 4; nt++) {
            biasA[nt] = k2b[c0 + nt * 8 + tg * 2];
            biasB[nt] = k2b[c0 + nt * 8 + tg * 2 + 1];
        }

        #pragma unroll
        for (int rt = 0; rt < 4; rt++) {
            const int r0 = rowH * 64 + rt * 16;
            float acc[4][4];
            #pragma unroll
            for (int nt = 0; nt < 4; nt++)
                acc[nt][0] = acc[nt][1] = acc[nt][2] = acc[nt][3] = 0.f;
            #pragma unroll
            for (int ks = 0; ks < 8; ks++) {
                uint32_t a[4];
                ldsm_x4(a, sA1 + ((r0 + lrow) * ST + ks * 16 + lcol) * 2);
                #pragma unroll
                for (int nt = 0; nt < 4; nt++)
                    mma16816(acc[nt], a[0], a[1], a[2], a[3],
                             B2f[nt * 16 + ks * 2], B2f[nt * 16 + ks * 2 + 1]);
            }
            // permuted store: pos c0 + tg*8 + nt*2 + b <- col c0 + nt*8 + tg*2 + b
            uint32_t p0[4], p1[4];
            #pragma unroll
            for (int nt = 0; nt < 4; nt++) {
                __half2 h0 = __floats2half2_rn(
                    fmaxf(acc[nt][0] + biasA[nt], 0.f), fmaxf(acc[nt][1] + biasB[nt], 0.f));
                __half2 h1 = __floats2half2_rn(
                    fmaxf(acc[nt][2] + biasA[nt], 0.f), fmaxf(acc[nt][3] + biasB[nt], 0.f));
                p0[nt] = *(uint32_t*)&h0;
                p1[nt] = *(uint32_t*)&h1;
            }
            *(uint4*)&A2[(r0 + g) * ST + c0 + tg * 8] =
                make_uint4(p0[0], p0[1], p0[2], p0[3]);
            *(uint4*)&A2[(r0 + g + 8) * ST + c0 + tg * 8] =
                make_uint4(p1[0], p1[1], p1[2], p1[3]);
        }
    }
    __syncthreads();

    // ---- stage 3: W = e2 @ k3_w + k3_b -> permuted fp16 global (128-bit cs) ----
    {
        const int c0 = warp * 32;
        uint32_t B3f[64];                  // [nt*16 + ks*2 + h]
        {
            const uint4* tp = ((const uint4*)d_k3p) + (warp * 16) * 32 + lane;
            #pragma unroll
            for (int c = 0; c < 16; c++) {
                uint4 v = tp[c * 32];
                B3f[c * 4 + 0] = v.x; B3f[c * 4 + 1] = v.y;
                B3f[c * 4 + 2] = v.z; B3f[c * 4 + 3] = v.w;
            }
        }
        float biasA[4], biasB[4];
        #pragma unroll
        for (int nt = 0; nt < 4; nt++) {
            biasA[nt] = k3b[c0 + nt * 8 + tg * 2];
            biasB[nt] = k3b[c0 + nt * 8 + tg * 2 + 1];
        }

        #pragma unroll
        for (int rt = 0; rt < 8; rt++) {
            const int r0 = rt * 16;
            float acc[4][4];
            #pragma unroll
            for (int nt = 0; nt < 4; nt++)
                acc[nt][0] = acc[nt][1] = acc[nt][2] = acc[nt][3] = 0.f;
            #pragma unroll
            for (int ks = 0; ks < 8; ks++) {
                uint32_t a[4];
                ldsm_x4(a, sA2 + ((r0 + lrow) * ST + ks * 16 + lcol) * 2);
                #pragma unroll
                for (int nt = 0; nt < 4; nt++)
                    mma16816(acc[nt], a[0], a[1], a[2], a[3],
                             B3f[nt * 16 + ks * 2], B3f[nt * 16 + ks * 2 + 1]);
            }
            // permuted W store: pos (c0 + tg*8 + nt*2 + b) holds logical col
            // (c0 + nt*8 + tg*2 + b). Per row-half one uint4.
            uint32_t p0[4], p1[4];
            #pragma unroll
            for (int nt = 0; nt < 4; nt++) {
                __half2 h0 = __floats2half2_rn(acc[nt][0] + biasA[nt], acc[nt][1] + biasB[nt]);
                __half2 h1 = __floats2half2_rn(acc[nt][2] + biasA[nt], acc[nt][3] + biasB[nt]);
                p0[nt] = *(uint32_t*)&h0;
                p1[nt] = *(uint32_t*)&h1;
            }
            __half* base0 = d_W + (ebase + r0 + g) * 256 + c0 + tg * 8;
            __half* base1 = d_W + (ebase + r0 + g + 8) * 256 + c0 + tg * 8;
            stcs_v4(base0, p0[0], p0[1], p0[2], p0[3]);
            stcs_v4(base1, p1[0], p1[1], p1[2], p1[3]);
        }
    }
}

// msg = h[src] @ W_e (permuted layout) ; vector scatter-add into agg[dst]
__global__ void k_conv(const void* __restrict__ ei, const float* __restrict__ hin)
{
    long long e = (long long)blockIdx.x * 32 + (threadIdx.x >> 3);
    int o = threadIdx.x & 7;           // output half2 index (cols 2o, 2o+1)
    if (e >= EE) return;
    long long src, dst;
    if (d_is64) {
        const long long* p = (const long long*)ei;
        src = p[e]; dst = p[EE + e];
    } else {
        const int* p = (const int*)ei;
        src = p[e]; dst = p[EE + e];
    }
    const float4* hr4 = (const float4*)(hin + src * EMB);
    float4 h0 = hr4[0], h1 = hr4[1], h2 = hr4[2], h3 = hr4[3];
    float hr[16] = {h0.x,h0.y,h0.z,h0.w, h1.x,h1.y,h1.z,h1.w,
                    h2.x,h2.y,h2.z,h2.w, h3.x,h3.y,h3.z,h3.w};
    const __half2* Wr = (const __half2*)(d_W + e * 256);
    const int oa = (o & 3) * 4 + (o >> 2);   // permutation constant for this o
    float mx = 0.f, my = 0.f;
    #pragma unroll
    for (int i = 0; i < 16; i++) {
        // inverse fragment permutation: logical col i*16+2o(+1)
        int idx = (i >> 1) * 16 + (i & 1) * 2 + oa;
        float2 wf = __half22float2(__ldcs(&Wr[idx]));
        mx = fmaf(hr[i], wf.x, mx);
        my = fmaf(hr[i], wf.y, my);
    }
    float* dp = &d_agg[dst * EMB + 2 * o];
    asm volatile("red.global.add.v2.f32 [%0], {%1,%2};\n"
                 :: "l"(dp), "f"(mx), "f"(my) : "memory");
}

// h_out = relu(agg/denom + h_in @ root_w + conv_b); zero agg for next round
__global__ void k_update(const float* __restrict__ hin, float* __restrict__ hout,
                         const float* __restrict__ root_w, const float* __restrict__ conv_b)
{
    int t = blockIdx.x * blockDim.x + threadIdx.x;
    if (t >= NN * EMB) return;
    int n = t >> 4, o = t & 15;
    float denom = fmaxf(d_cnt[n], 1.f);
    float v = d_agg[t] / denom;
    const float* hr = hin + n * EMB;
    #pragma unroll
    for (int i = 0; i < 16; i++) v = fmaf(hr[i], root_w[i * EMB + o], v);
    v += conv_b[o];
    hout[t] = fmaxf(v, 0.f);
    d_agg[t] = 0.f;
}

__global__ void k_out(const float* __restrict__ hin,
                      const float* __restrict__ inv_w, const float* __restrict__ inv_b,
                      float* __restrict__ out)
{
    int t = blockIdx.x * blockDim.x + threadIdx.x;
    if (t >= NN * 3) return;
    int n = t / 3, f = t % 3;
    float v = inv_b[f];
    const float* hr = hin + n * EMB;
    #pragma unroll
    for (int i = 0; i < 16; i++) v = fmaf(hr[i], inv_w[i * 3 + f], v);
    out[t] = v;
}

// ---------------- launcher ----------------
extern "C" void kernel_launch(void* const* d_in, const int* in_sizes, int n_in,
                              void* d_out, int out_size)
{
    const float* x      = (const float*)d_in[0];
    const void*  ei     = d_in[1];
    const float* ea     = (const float*)d_in[2];
    const float* emb_w  = (const float*)d_in[3];
    const float* emb_b  = (const float*)d_in[4];
    const float* k1_w   = (const float*)d_in[5];
    const float* k1_b   = (const float*)d_in[6];
    const float* k2_w   = (const float*)d_in[7];
    const float* k2_b   = (const float*)d_in[8];
    const float* k3_w   = (const float*)d_in[9];
    const float* k3_b   = (const float*)d_in[10];
    const float* root_w = (const float*)d_in[11];
    const float* conv_b = (const float*)d_in[12];
    const float* inv_w  = (const float*)d_in[13];
    const float* inv_b  = (const float*)d_in[14];
    float* out = (float*)d_out;

    const int ST = KW + 8;
    const int smemBytes = (2 * 128 * ST + 128 * 8) * (int)sizeof(__half);  // 71680
    cudaFuncSetAttribute(k_mlp, cudaFuncAttributeMaxDynamicSharedMemorySize, smemBytes);

    static float* hA = nullptr;
    static float* hB = nullptr;
    if (!hA) {
        cudaGetSymbolAddress((void**)&hA, d_hA);
        cudaGetSymbolAddress((void**)&hB, d_hB);
    }

    // k_mlp kept in the ncu-profiled launch slot.
    k_detect<<<1, 256>>>((const int*)ei);
    k_prep<<<(8192 + 16384 + 255) / 256, 256>>>(k2_w, k3_w);
    k_init<<<(NN * EMB + 255) / 256, 256>>>(x, emb_w, emb_b);
    k_mlp<<<EE / 128, 256, smemBytes>>>(ea, k1_w, k1_b, k2_b, k3_b);
    k_cnt<<<(EE + 255) / 256, 256>>>(ei);

    float* hin  = hA;
    float* hout = hB;
    for (int it = 0; it < NCONV; it++) {
        k_conv<<<EE / 32, 256>>>(ei, hin);
        k_update<<<(NN * EMB + 255) / 256, 256>>>(hin, hout, root_w, conv_b);
        float* tmp = hin; hin = hout; hout = tmp;
    }
    k_out<<<(NN * 3 + 255) / 256, 256>>>(hin, inv_w, inv_b, out);
}

// round 10
// speedup vs baseline: 3.5677x; 1.0077x over previous
#include <cuda_runtime.h>
#include <cuda_fp16.h>
#include <cstdint>

#define NN   50000
#define EE   800000
#define EMB  16
#define KW   128
#define NCONV 4

// ---------------- device scratch (no cudaMalloc allowed) ----------------
__device__ __half  d_W[(size_t)EE * 256];     // per-edge 16x16 W, fragment-permuted fp16
__device__ float   d_hA[NN * EMB];
__device__ float   d_hB[NN * EMB];
__device__ float   d_agg[NN * EMB];
__device__ float   d_cnt[NN];
__device__ __half2 d_k2p[8192];               // k2 fragments: [colQ][chunk16][lane][4]
__device__ __half2 d_k3p[16384];              // k3 fragments: [warp][chunk16][lane][4]
__device__ int     d_is64;

// ---------------- helpers ----------------
__device__ __forceinline__ void mma16816(float* c,
    uint32_t a0, uint32_t a1, uint32_t a2, uint32_t a3,
    uint32_t b0, uint32_t b1)
{
    asm volatile(
        "mma.sync.aligned.m16n8k16.row.col.f32.f16.f16.f32 "
        "{%0,%1,%2,%3},{%4,%5,%6,%7},{%8,%9},{%0,%1,%2,%3};\n"
        : "+f"(c[0]), "+f"(c[1]), "+f"(c[2]), "+f"(c[3])
        : "r"(a0), "r"(a1), "r"(a2), "r"(a3), "r"(b0), "r"(b1));
}

__device__ __forceinline__ void mma16808(float* c, uint32_t a0, uint32_t a1, uint32_t b0)
{
    asm volatile(
        "mma.sync.aligned.m16n8k8.row.col.f32.f16.f16.f32 "
        "{%0,%1,%2,%3},{%4,%5},{%6},{%0,%1,%2,%3};\n"
        : "+f"(c[0]), "+f"(c[1]), "+f"(c[2]), "+f"(c[3])
        : "r"(a0), "r"(a1), "r"(b0));
}

__device__ __forceinline__ void ldsm_x4(uint32_t* a, uint32_t saddr)
{
    asm volatile(
        "ldmatrix.sync.aligned.m8n8.x4.shared.b16 {%0,%1,%2,%3}, [%4];\n"
        : "=r"(a[0]), "=r"(a[1]), "=r"(a[2]), "=r"(a[3]) : "r"(saddr));
}

__device__ __forceinline__ void ldsm_x2(uint32_t* a, uint32_t saddr)
{
    asm volatile(
        "ldmatrix.sync.aligned.m8n8.x2.shared.b16 {%0,%1}, [%2];\n"
        : "=r"(a[0]), "=r"(a[1]) : "r"(saddr));
}

__device__ __forceinline__ void stcs_v4(void* p, uint32_t x, uint32_t y, uint32_t z, uint32_t w)
{
    asm volatile("st.global.cs.v4.b32 [%0], {%1,%2,%3,%4};\n"
                 :: "l"(p), "r"(x), "r"(y), "r"(z), "r"(w) : "memory");
}

// ---------------- kernels ----------------

__global__ void k_detect(const int* __restrict__ ei)
{
    __shared__ int anynz;
    if (threadIdx.x == 0) anynz = 0;
    __syncthreads();
    int v = ei[2 * threadIdx.x + 1];
    if (v != 0) atomicOr(&anynz, 1);
    __syncthreads();
    if (threadIdx.x == 0) d_is64 = (anynz == 0) ? 1 : 0;
}

// Fused setup: blocks [0,3125) do h0 init + agg/cnt zero; blocks [3125,3221)
// build the fragment-permuted fp16 B tables for layers 2 and 3.
// K indices incorporate the permuted A1/A2 smem layouts (see k_mlp epilogues):
//   stage2: k = ks*16 + (tg&1)*8 + (h*2 + (tg>>1))*2    (A1 perm: pos=tg*4+j)
//   stage3: k = (ks>>1)*32 + tg*8 + ((ks&1)*2 + h)*2    (A2 perm: pos=tg*8+nt*2+b)
__global__ void k_setup(const float* __restrict__ x,
                        const float* __restrict__ emb_w,
                        const float* __restrict__ emb_b,
                        const float* __restrict__ k2w,
                        const float* __restrict__ k3w)
{
    if (blockIdx.x < 3125) {
        int t = blockIdx.x * 256 + threadIdx.x;
        if (t >= NN * EMB) return;
        int n = t >> 4, o = t & 15;
        float v = emb_b[o];
        #pragma unroll
        for (int f = 0; f < 3; f++) v += x[n * 3 + f] * emb_w[f * EMB + o];
        d_hA[t]  = v;
        d_agg[t] = 0.f;
        if (o == 0) d_cnt[n] = 0.f;
        return;
    }
    int t = (blockIdx.x - 3125) * 256 + threadIdx.x;
    if (t < 8192) {            // stage-2 table: 4 colQ x 16 chunks x 32 lanes x 4
        int j = t & 3, l = (t >> 2) & 31, c = (t >> 7) & 15, cq = t >> 11;
        int q = c * 4 + j;                       // nt*16 + ks*2 + h
        int nt = q >> 4, ks = (q >> 1) & 7, h = q & 1;
        int g = l >> 2, tg = l & 3;
        int n = cq * 32 + nt * 8 + g;
        int k = ks * 16 + (tg & 1) * 8 + (h * 2 + (tg >> 1)) * 2;
        d_k2p[t] = __floats2half2_rn(k2w[k * KW + n], k2w[(k + 1) * KW + n]);
    } else if (t < 8192 + 16384) {  // stage-3 table: 8 warps x 16 chunks x 32 lanes x 4
        int t2 = t - 8192;
        int j = t2 & 3, l = (t2 >> 2) & 31, c = (t2 >> 7) & 15, w = t2 >> 11;
        int q = c * 4 + j;
        int nt = q >> 4, ks = (q >> 1) & 7, h = q & 1;
        int g = l >> 2, tg = l & 3;
        int n = w * 32 + nt * 8 + g;
        int k = (ks >> 1) * 32 + tg * 8 + ((ks & 1) * 2 + h) * 2;
        d_k3p[t2] = __floats2half2_rn(k3w[k * 256 + n], k3w[(k + 1) * 256 + n]);
    }
}

// Fused edge-MLP: 128 edges/block, all layers on tensor cores.
// Stage0 also performs the scatter-mean edge counting (fused former k_cnt).
__global__ __launch_bounds__(256, 2) void k_mlp(
    const void* __restrict__ ei,
    const float* __restrict__ ea,
    const float* __restrict__ k1w, const float* __restrict__ k1b,
    const float* __restrict__ k2b, const float* __restrict__ k3b)
{
    const int ST = KW + 8;                 // smem row stride in halves (272B, 16B-mult)
    extern __shared__ __half sm[];
    __half* A1 = sm;                       // e1: 128 x ST (K-permuted per 16-block)
    __half* A2 = A1 + 128 * ST;            // e2: 128 x ST (K-permuted per 32-block)
    __half* EA = A2 + 128 * ST;            // ea fp16: 128 x 8

    const int tid  = threadIdx.x;
    const int warp = tid >> 5;
    const int lane = tid & 31;
    const int g    = lane >> 2;
    const int tg   = lane & 3;
    const long long ebase = (long long)blockIdx.x * 128;

    const uint32_t sA1 = (uint32_t)__cvta_generic_to_shared(A1);
    const uint32_t sA2 = (uint32_t)__cvta_generic_to_shared(A2);
    const uint32_t sEA = (uint32_t)__cvta_generic_to_shared(EA);
    const uint32_t lrow = (lane & 15);
    const uint32_t lcol = (lane >> 4) * 8;

    // ---- stage 0: ea -> fp16 smem tile [128 x 8]; fused edge count ----
    if (tid < 128) {
        const float* er = ea + (ebase + tid) * 6;
        float a0 = er[0], a1 = er[1], a2 = er[2], a3 = er[3], a4 = er[4], a5 = er[5];
        __half2* row = (__half2*)(EA + tid * 8);
        row[0] = __floats2half2_rn(a0, a1);
        row[1] = __floats2half2_rn(a2, a3);
        row[2] = __floats2half2_rn(a4, a5);
        row[3] = __floats2half2_rn(0.f, 0.f);
        // fused k_cnt: one atomic per edge
        long long dst;
        if (d_is64) dst = ((const long long*)ei)[EE + ebase + tid];
        else        dst = ((const int*)ei)[EE + ebase + tid];
        atomicAdd(&d_cnt[dst], 1.f);
    }

    // ---- stage 1: e1 = relu(ea @ k1_w + k1_b) via m16n8k8 -> permuted A1 ----
    {
        const int c0 = warp * 16;
        uint32_t B1[2];
        #pragma unroll
        for (int nt = 0; nt < 2; nt++) {
            int n  = c0 + nt * 8 + g;
            int k0 = tg * 2;
            float f0 = (k0     < 6) ? k1w[k0 * KW + n]       : 0.f;
            float f1 = (k0 + 1 < 6) ? k1w[(k0 + 1) * KW + n] : 0.f;
            __half2 hv = __floats2half2_rn(f0, f1);
            B1[nt] = *(uint32_t*)&hv;
        }
        float bias0 = k1b[c0 + tg * 2],     bias1 = k1b[c0 + tg * 2 + 1];
        float bias2 = k1b[c0 + 8 + tg * 2], bias3 = k1b[c0 + 8 + tg * 2 + 1];
        __syncthreads();   // EA tile ready

        #pragma unroll
        for (int rt = 0; rt < 8; rt++) {
            uint32_t a[2];
            ldsm_x2(a, sEA + (uint32_t)(rt * 16 + lrow) * 16);
            float acc0[4] = {0.f, 0.f, 0.f, 0.f};
            float acc1[4] = {0.f, 0.f, 0.f, 0.f};
            mma16808(acc0, a[0], a[1], B1[0]);
            mma16808(acc1, a[0], a[1], B1[1]);
            int r0 = rt * 16;
            // permuted store: pos c0 + tg*4 + {0,1,2,3} <- cols {tg*2,tg*2+1,8+tg*2,8+tg*2+1}
            __half2 q0 = __floats2half2_rn(
                fmaxf(acc0[0] + bias0, 0.f), fmaxf(acc0[1] + bias1, 0.f));
            __half2 q1 = __floats2half2_rn(
                fmaxf(acc1[0] + bias2, 0.f), fmaxf(acc1[1] + bias3, 0.f));
            *(uint2*)&A1[(r0 + g) * ST + c0 + tg * 4] =
                make_uint2(*(uint32_t*)&q0, *(uint32_t*)&q1);
            __half2 q2 = __floats2half2_rn(
                fmaxf(acc0[2] + bias0, 0.f), fmaxf(acc0[3] + bias1, 0.f));
            __half2 q3 = __floats2half2_rn(
                fmaxf(acc1[2] + bias2, 0.f), fmaxf(acc1[3] + bias3, 0.f));
            *(uint2*)&A1[(r0 + g + 8) * ST + c0 + tg * 4] =
                make_uint2(*(uint32_t*)&q2, *(uint32_t*)&q3);
        }
    }
    __syncthreads();

    // ---- stage 2: e2 = relu(e1 @ k2_w + k2_b), 2D warp tiling ----
    {
        const int colQ = warp & 3;         // 32-col quarter
        const int rowH = warp >> 2;        // 64-row half
        const int c0 = colQ * 32;
        uint32_t B2f[64];                  // [nt*16 + ks*2 + h]
        {
            const uint4* tp = ((const uint4*)d_k2p) + (colQ * 16) * 32 + lane;
            #pragma unroll
            for (int c = 0; c < 16; c++) {
                uint4 v = tp[c * 32];
                B2f[c * 4 + 0] = v.x; B2f[c * 4 + 1] = v.y;
                B2f[c * 4 + 2] = v.z; B2f[c * 4 + 3] = v.w;
            }
        }
        float biasA[4], biasB[4];
        #pragma unroll
        for (int nt = 0; nt < 4; nt++) {
            biasA[nt] = k2b[c0 + nt * 8 + tg * 2];
            biasB[nt] = k2b[c0 + nt * 8 + tg * 2 + 1];
        }

        #pragma unroll
        for (int rt = 0; rt < 4; rt++) {
            const int r0 = rowH * 64 + rt * 16;
            float acc[4][4];
            #pragma unroll
            for (int nt = 0; nt < 4; nt++)
                acc[nt][0] = acc[nt][1] = acc[nt][2] = acc[nt][3] = 0.f;
            #pragma unroll
            for (int ks = 0; ks < 8; ks++) {
                uint32_t a[4];
                ldsm_x4(a, sA1 + ((r0 + lrow) * ST + ks * 16 + lcol) * 2);
                #pragma unroll
                for (int nt = 0; nt < 4; nt++)
                    mma16816(acc[nt], a[0], a[1], a[2], a[3],
                             B2f[nt * 16 + ks * 2], B2f[nt * 16 + ks * 2 + 1]);
            }
            // permuted store: pos c0 + tg*8 + nt*2 + b <- col c0 + nt*8 + tg*2 + b
            uint32_t p0[4], p1[4];
            #pragma unroll
            for (int nt = 0; nt < 4; nt++) {
                __half2 h0 = __floats2half2_rn(
                    fmaxf(acc[nt][0] + biasA[nt], 0.f), fmaxf(acc[nt][1] + biasB[nt], 0.f));
                __half2 h1 = __floats2half2_rn(
                    fmaxf(acc[nt][2] + biasA[nt], 0.f), fmaxf(acc[nt][3] + biasB[nt], 0.f));
                p0[nt] = *(uint32_t*)&h0;
                p1[nt] = *(uint32_t*)&h1;
            }
            *(uint4*)&A2[(r0 + g) * ST + c0 + tg * 8] =
                make_uint4(p0[0], p0[1], p0[2], p0[3]);
            *(uint4*)&A2[(r0 + g + 8) * ST + c0 + tg * 8] =
                make_uint4(p1[0], p1[1], p1[2], p1[3]);
        }
    }
    __syncthreads();

    // ---- stage 3: W = e2 @ k3_w + k3_b -> permuted fp16 global (128-bit cs) ----
    {
        const int c0 = warp * 32;
        uint32_t B3f[64];                  // [nt*16 + ks*2 + h]
        {
            const uint4* tp = ((const uint4*)d_k3p) + (warp * 16) * 32 + lane;
            #pragma unroll
            for (int c = 0; c < 16; c++) {
                uint4 v = tp[c * 32];
                B3f[c * 4 + 0] = v.x; B3f[c * 4 + 1] = v.y;
                B3f[c * 4 + 2] = v.z; B3f[c * 4 + 3] = v.w;
            }
        }
        float biasA[4], biasB[4];
        #pragma unroll
        for (int nt = 0; nt < 4; nt++) {
            biasA[nt] = k3b[c0 + nt * 8 + tg * 2];
            biasB[nt] = k3b[c0 + nt * 8 + tg * 2 + 1];
        }

        #pragma unroll
        for (int rt = 0; rt < 8; rt++) {
            const int r0 = rt * 16;
            float acc[4][4];
            #pragma unroll
            for (int nt = 0; nt < 4; nt++)
                acc[nt][0] = acc[nt][1] = acc[nt][2] = acc[nt][3] = 0.f;
            #pragma unroll
            for (int ks = 0; ks < 8; ks++) {
                uint32_t a[4];
                ldsm_x4(a, sA2 + ((r0 + lrow) * ST + ks * 16 + lcol) * 2);
                #pragma unroll
                for (int nt = 0; nt < 4; nt++)
                    mma16816(acc[nt], a[0], a[1], a[2], a[3],
                             B3f[nt * 16 + ks * 2], B3f[nt * 16 + ks * 2 + 1]);
            }
            // permuted W store: pos (c0 + tg*8 + nt*2 + b) holds logical col
            // (c0 + nt*8 + tg*2 + b). Per row-half one uint4.
            uint32_t p0[4], p1[4];
            #pragma unroll
            for (int nt = 0; nt < 4; nt++) {
                __half2 h0 = __floats2half2_rn(acc[nt][0] + biasA[nt], acc[nt][1] + biasB[nt]);
                __half2 h1 = __floats2half2_rn(acc[nt][2] + biasA[nt], acc[nt][3] + biasB[nt]);
                p0[nt] = *(uint32_t*)&h0;
                p1[nt] = *(uint32_t*)&h1;
            }
            __half* base0 = d_W + (ebase + r0 + g) * 256 + c0 + tg * 8;
            __half* base1 = d_W + (ebase + r0 + g + 8) * 256 + c0 + tg * 8;
            stcs_v4(base0, p0[0], p0[1], p0[2], p0[3]);
            stcs_v4(base1, p1[0], p1[1], p1[2], p1[3]);
        }
    }
}

// msg = h[src] @ W_e (permuted layout) ; vector scatter-add into agg[dst]
__global__ void k_conv(const void* __restrict__ ei, const float* __restrict__ hin)
{
    long long e = (long long)blockIdx.x * 32 + (threadIdx.x >> 3);
    int o = threadIdx.x & 7;           // output half2 index (cols 2o, 2o+1)
    if (e >= EE) return;
    long long src, dst;
    if (d_is64) {
        const long long* p = (const long long*)ei;
        src = p[e]; dst = p[EE + e];
    } else {
        const int* p = (const int*)ei;
        src = p[e]; dst = p[EE + e];
    }
    const float4* hr4 = (const float4*)(hin + src * EMB);
    float4 h0 = hr4[0], h1 = hr4[1], h2 = hr4[2], h3 = hr4[3];
    float hr[16] = {h0.x,h0.y,h0.z,h0.w, h1.x,h1.y,h1.z,h1.w,
                    h2.x,h2.y,h2.z,h2.w, h3.x,h3.y,h3.z,h3.w};
    const __half2* Wr = (const __half2*)(d_W + e * 256);
    const int oa = (o & 3) * 4 + (o >> 2);   // permutation constant for this o
    float mx = 0.f, my = 0.f;
    #pragma unroll
    for (int i = 0; i < 16; i++) {
        // inverse fragment permutation: logical col i*16+2o(+1)
        int idx = (i >> 1) * 16 + (i & 1) * 2 + oa;
        float2 wf = __half22float2(__ldcs(&Wr[idx]));
        mx = fmaf(hr[i], wf.x, mx);
        my = fmaf(hr[i], wf.y, my);
    }
    float* dp = &d_agg[dst * EMB + 2 * o];
    asm volatile("red.global.add.v2.f32 [%0], {%1,%2};\n"
                 :: "l"(dp), "f"(mx), "f"(my) : "memory");
}

// h_out = relu(agg/denom + h_in @ root_w + conv_b); zero agg for next round
__global__ void k_update(const float* __restrict__ hin, float* __restrict__ hout,
                         const float* __restrict__ root_w, const float* __restrict__ conv_b)
{
    int t = blockIdx.x * blockDim.x + threadIdx.x;
    if (t >= NN * EMB) return;
    int n = t >> 4, o = t & 15;
    float denom = fmaxf(d_cnt[n], 1.f);
    float v = d_agg[t] / denom;
    const float* hr = hin + n * EMB;
    #pragma unroll
    for (int i = 0; i < 16; i++) v = fmaf(hr[i], root_w[i * EMB + o], v);
    v += conv_b[o];
    hout[t] = fmaxf(v, 0.f);
    d_agg[t] = 0.f;
}

__global__ void k_out(const float* __restrict__ hin,
                      const float* __restrict__ inv_w, const float* __restrict__ inv_b,
                      float* __restrict__ out)
{
    int t = blockIdx.x * blockDim.x + threadIdx.x;
    if (t >= NN * 3) return;
    int n = t / 3, f = t % 3;
    float v = inv_b[f];
    const float* hr = hin + n * EMB;
    #pragma unroll
    for (int i = 0; i < 16; i++) v = fmaf(hr[i], inv_w[i * 3 + f], v);
    out[t] = v;
}

// ---------------- launcher ----------------
extern "C" void kernel_launch(void* const* d_in, const int* in_sizes, int n_in,
                              void* d_out, int out_size)
{
    const float* x      = (const float*)d_in[0];
    const void*  ei     = d_in[1];
    const float* ea     = (const float*)d_in[2];
    const float* emb_w  = (const float*)d_in[3];
    const float* emb_b  = (const float*)d_in[4];
    const float* k1_w   = (const float*)d_in[5];
    const float* k1_b   = (const float*)d_in[6];
    const float* k2_w   = (const float*)d_in[7];
    const float* k2_b   = (const float*)d_in[8];
    const float* k3_w   = (const float*)d_in[9];
    const float* k3_b   = (const float*)d_in[10];
    const float* root_w = (const float*)d_in[11];
    const float* conv_b = (const float*)d_in[12];
    const float* inv_w  = (const float*)d_in[13];
    const float* inv_b  = (const float*)d_in[14];
    float* out = (float*)d_out;

    const int ST = KW + 8;
    const int smemBytes = (2 * 128 * ST + 128 * 8) * (int)sizeof(__half);  // 71680
    cudaFuncSetAttribute(k_mlp, cudaFuncAttributeMaxDynamicSharedMemorySize, smemBytes);

    static float* hA = nullptr;
    static float* hB = nullptr;
    if (!hA) {
        cudaGetSymbolAddress((void**)&hA, d_hA);
        cudaGetSymbolAddress((void**)&hB, d_hB);
    }

    // Launch order: detect(1), setup(2), mlp(3), conv1(4) — puts k_conv in the
    // ncu-profiled slot (first direct look at the conv loop).
    k_detect<<<1, 256>>>((const int*)ei);
    k_setup<<<3125 + 96, 256>>>(x, emb_w, emb_b, k2_w, k3_w);
    k_mlp<<<EE / 128, 256, smemBytes>>>(ei, ea, k1_w, k1_b, k2_b, k3_b);

    float* hin  = hA;
    float* hout = hB;
    for (int it = 0; it < NCONV; it++) {
        k_conv<<<EE / 32, 256>>>(ei, hin);
        k_update<<<(NN * EMB + 255) / 256, 256>>>(hin, hout, root_w, conv_b);
        float* tmp = hin; hin = hout; hout = tmp;
    }
    k_out<<<(NN * 3 + 255) / 256, 256>>>(hin, inv_w, inv_b, out);
}